// round 12
// baseline (speedup 1.0000x reference)
#include <cuda_runtime.h>
#include <cstdint>

typedef unsigned long long ull;

// Problem constants (fixed shapes per reference)
#define NN    100000
#define EE    1600000
#define CINn  64
#define COUTn 128
#define SCAN_B 512

// ---------------- scratch (static device globals; no runtime alloc) ----------------
__device__ float g_agg0[(size_t)NN * CINn];
__device__ float g_agg1[(size_t)NN * COUTn];
__device__ float g_h0[(size_t)NN * COUTn];
__device__ float g_h1[(size_t)NN * COUTn];
__device__ float g_r[(size_t)NN * COUTn];
__device__ float g_stats[4 * COUTn];
__device__ float g_bnp[4 * COUTn];
// CSR scratch
__device__ int g_deg[NN];
__device__ int g_lscan[NN];
__device__ int g_part[256];
__device__ int g_rowptr[NN + 1];
__device__ int g_cursor[NN];
__device__ int g_eidx[EE];

// ---------------- packed fp32x2 FMA ----------------
#define FMA2(acc, a, w) \
    asm("fma.rn.f32x2 %0, %1, %2, %0;" : "+l"(acc) : "l"(a), "l"(w))

__device__ __forceinline__ ull dup2(float f) {
    ull r;
    asm("mov.b64 %0, {%1, %1};" : "=l"(r) : "f"(f));
    return r;
}

union F2 { ull u; float2 f; };
union W4 { float4 v; ull u[2]; };

// =============================================================================
// CSR build: histogram -> scan -> fill
// =============================================================================
__global__ void hist_kernel(const int* __restrict__ dst, int* __restrict__ deg, int E) {
    const int e = blockIdx.x * blockDim.x + threadIdx.x;
    if (e < E) atomicAdd(&deg[dst[e]], 1);
}

__global__ void scan1_kernel(const int* __restrict__ deg, int* __restrict__ lscan,
                             int* __restrict__ part, int N) {
    __shared__ int sh[SCAN_B];
    const int i = blockIdx.x * SCAN_B + threadIdx.x;
    const int v = (i < N) ? deg[i] : 0;
    sh[threadIdx.x] = v;
    __syncthreads();
#pragma unroll
    for (int off = 1; off < SCAN_B; off <<= 1) {
        int t = (threadIdx.x >= off) ? sh[threadIdx.x - off] : 0;
        __syncthreads();
        sh[threadIdx.x] += t;
        __syncthreads();
    }
    if (i < N) lscan[i] = sh[threadIdx.x] - v;
    if (threadIdx.x == SCAN_B - 1) part[blockIdx.x] = sh[threadIdx.x];
}

__global__ void scan2_kernel(int* __restrict__ part, int nb) {
    __shared__ int sh[256];
    const int v = (threadIdx.x < nb) ? part[threadIdx.x] : 0;
    sh[threadIdx.x] = v;
    __syncthreads();
#pragma unroll
    for (int off = 1; off < 256; off <<= 1) {
        int t = (threadIdx.x >= off) ? sh[threadIdx.x - off] : 0;
        __syncthreads();
        sh[threadIdx.x] += t;
        __syncthreads();
    }
    if (threadIdx.x < nb) part[threadIdx.x] = sh[threadIdx.x] - v;
}

__global__ void scan3_kernel(const int* __restrict__ lscan, const int* __restrict__ part,
                             int* __restrict__ rowptr, int* __restrict__ cursor,
                             int N, int E) {
    const int i = blockIdx.x * blockDim.x + threadIdx.x;
    if (i < N) {
        const int r = lscan[i] + part[i / SCAN_B];
        rowptr[i] = r;
        cursor[i] = r;
    }
    if (i == 0) rowptr[N] = E;
}

__global__ void fill_kernel(const int* __restrict__ src, const int* __restrict__ dst,
                            int* __restrict__ cursor, int* __restrict__ eidx, int E) {
    const int e = blockIdx.x * blockDim.x + threadIdx.x;
    if (e < E) {
        const int pos = atomicAdd(&cursor[dst[e]], 1);
        eidx[pos] = src[e];
    }
}

// =============================================================================
// Gather (layer 0): agg0[n] = sum x[src], 8-edge unrolled (MLP=8), C4=16
// =============================================================================
__global__ void gather0_kernel(const int* __restrict__ rowptr, const int* __restrict__ eidx,
                               const float4* __restrict__ feat, float4* __restrict__ agg,
                               int N) {
    const int g = threadIdx.x >> 4;
    const int c = threadIdx.x & 15;
    const int node = blockIdx.x * 16 + g;
    if (node >= N) return;
    const int beg = rowptr[node];
    const int end = rowptr[node + 1];
    float4 acc = make_float4(0.f, 0.f, 0.f, 0.f);
    int e = beg;
    for (; e + 7 < end; e += 8) {
        int s[8];
#pragma unroll
        for (int j = 0; j < 8; j++) s[j] = __ldg(eidx + e + j);
        float4 v[8];
#pragma unroll
        for (int j = 0; j < 8; j++) v[j] = feat[(size_t)s[j] * 16 + c];
#pragma unroll
        for (int j = 0; j < 8; j++) {
            acc.x += v[j].x; acc.y += v[j].y; acc.z += v[j].z; acc.w += v[j].w;
        }
    }
    for (; e < end; e++) {
        const int s = __ldg(eidx + e);
        const float4 v = feat[(size_t)s * 16 + c];
        acc.x += v.x; acc.y += v.y; acc.z += v.z; acc.w += v.w;
    }
    agg[(size_t)node * 16 + c] = acc;
}

// =============================================================================
// Gather (layer 1) with fused bn+relu: agg1[n] = sum relu(bn(h0[src])),
// 8-edge unrolled (MLP=8), C4=32
// =============================================================================
__global__ void gather1_kernel(const int* __restrict__ rowptr, const int* __restrict__ eidx,
                               const float4* __restrict__ h0, const float* __restrict__ bnp,
                               float4* __restrict__ agg, int N) {
    const int g = threadIdx.x >> 5;
    const int c = threadIdx.x & 31;
    const int node = blockIdx.x * 8 + g;
    if (node >= N) return;
    const float sc0 = bnp[c * 4 + 0], sh0 = bnp[128 + c * 4 + 0];
    const float sc1 = bnp[c * 4 + 1], sh1 = bnp[128 + c * 4 + 1];
    const float sc2 = bnp[c * 4 + 2], sh2 = bnp[128 + c * 4 + 2];
    const float sc3 = bnp[c * 4 + 3], sh3 = bnp[128 + c * 4 + 3];
    const int beg = rowptr[node];
    const int end = rowptr[node + 1];
    float4 acc = make_float4(0.f, 0.f, 0.f, 0.f);
    int e = beg;
    for (; e + 7 < end; e += 8) {
        int s[8];
#pragma unroll
        for (int j = 0; j < 8; j++) s[j] = __ldg(eidx + e + j);
        float4 v[8];
#pragma unroll
        for (int j = 0; j < 8; j++) v[j] = h0[(size_t)s[j] * 32 + c];
#pragma unroll
        for (int j = 0; j < 8; j++) {
            acc.x += fmaxf(fmaf(v[j].x, sc0, sh0), 0.f);
            acc.y += fmaxf(fmaf(v[j].y, sc1, sh1), 0.f);
            acc.z += fmaxf(fmaf(v[j].z, sc2, sh2), 0.f);
            acc.w += fmaxf(fmaf(v[j].w, sc3, sh3), 0.f);
        }
    }
    for (; e < end; e++) {
        const int s = __ldg(eidx + e);
        const float4 v = h0[(size_t)s * 32 + c];
        acc.x += fmaxf(fmaf(v.x, sc0, sh0), 0.f);
        acc.y += fmaxf(fmaf(v.y, sc1, sh1), 0.f);
        acc.z += fmaxf(fmaf(v.z, sc2, sh2), 0.f);
        acc.w += fmaxf(fmaf(v.w, sc3, sh3), 0.f);
    }
    agg[(size_t)node * 32 + c] = acc;
}

// =============================================================================
// Double-buffered fp32x2 GEMM: C = A@W1^T (+ B@W2^T) [+ C if accumC] + bias.
// BM=64, BN=128, BK=16, 256 threads. One sync per k-step; LDG prefetch.
// Optional fused BN stats; optional bnA (relu(bn(A)) on mat 0).
// =============================================================================
__global__ __launch_bounds__(256) void gemm_kernel(
    const float* __restrict__ A, const float* __restrict__ W1,
    const float* __restrict__ B, const float* __restrict__ W2,
    const float* __restrict__ bias, float* __restrict__ C,
    float* __restrict__ stats, const float* __restrict__ bnA,
    int Nn, int K, int accumC) {

    __shared__ alignas(16) ull As2[2][16 * 66];   // 2 x 8448 B
    __shared__ alignas(16) float Ws[2][16][128];  // 2 x 8192 B
    __shared__ float sh_sum[128];
    __shared__ float sh_sq[128];
    __shared__ float sbn[256];

    const int tid  = threadIdx.x;
    const int row0 = blockIdx.x * 64;
    const int warp = tid >> 5;
    const int lane = tid & 31;
    const int tm   = warp * 8;   // 8 rows per thread
    const int tn   = lane * 4;   // 4 cols per thread

    if (stats && tid < 128) { sh_sum[tid] = 0.f; sh_sq[tid] = 0.f; }
    if (bnA) sbn[tid] = bnA[tid];
    __syncthreads();

    const int ksPerMat = K >> 4;
    const int totSteps = (B != nullptr) ? 2 * ksPerMat : ksPerMat;

    // per-thread staging coordinates (fixed)
    const int am  = tid >> 2;            // A row within tile
    const int akq = (tid & 3) * 4;       // A k-quad
    const int wn  = tid >> 1;            // W n within tile
    const int wkq = (tid & 1) * 8;       // W k-oct

    auto LOAD = [&](int s, float4& va, float4& vw0, float4& vw1) {
        const int mt = (s >= ksPerMat) ? 1 : 0;
        const int k0 = (s - mt * ksPerMat) << 4;
        const float* Ap = mt ? B : A;
        const float* Wp = mt ? W2 : W1;
        const int rr = row0 + am;
        va = make_float4(0.f, 0.f, 0.f, 0.f);
        if (rr < Nn) va = *(const float4*)(Ap + (size_t)rr * K + k0 + akq);
        if (bnA && mt == 0) {
            const int cc = k0 + akq;
            va.x = fmaxf(fmaf(va.x, sbn[cc + 0], sbn[128 + cc + 0]), 0.f);
            va.y = fmaxf(fmaf(va.y, sbn[cc + 1], sbn[128 + cc + 1]), 0.f);
            va.z = fmaxf(fmaf(va.z, sbn[cc + 2], sbn[128 + cc + 2]), 0.f);
            va.w = fmaxf(fmaf(va.w, sbn[cc + 3], sbn[128 + cc + 3]), 0.f);
        }
        const float* wrow = Wp + (size_t)wn * K + k0 + wkq;
        vw0 = *(const float4*)(wrow);
        vw1 = *(const float4*)(wrow + 4);
    };
    auto STORE = [&](int b, const float4& va, const float4& vw0, const float4& vw1) {
        As2[b][(akq + 0) * 66 + am] = dup2(va.x);
        As2[b][(akq + 1) * 66 + am] = dup2(va.y);
        As2[b][(akq + 2) * 66 + am] = dup2(va.z);
        As2[b][(akq + 3) * 66 + am] = dup2(va.w);
        Ws[b][wkq + 0][wn] = vw0.x; Ws[b][wkq + 1][wn] = vw0.y;
        Ws[b][wkq + 2][wn] = vw0.z; Ws[b][wkq + 3][wn] = vw0.w;
        Ws[b][wkq + 4][wn] = vw1.x; Ws[b][wkq + 5][wn] = vw1.y;
        Ws[b][wkq + 6][wn] = vw1.z; Ws[b][wkq + 7][wn] = vw1.w;
    };

    ull acc2[8][2];
#pragma unroll
    for (int i = 0; i < 8; i++) { acc2[i][0] = 0ull; acc2[i][1] = 0ull; }

    // prologue
    {
        float4 va, vw0, vw1;
        LOAD(0, va, vw0, vw1);
        STORE(0, va, vw0, vw1);
    }
    __syncthreads();

    for (int s = 0; s < totSteps; s++) {
        const int cur = s & 1;
        float4 va, vw0, vw1;
        const bool more = (s + 1 < totSteps);
        if (more) LOAD(s + 1, va, vw0, vw1);   // LDG in flight during compute
#pragma unroll
        for (int kk = 0; kk < 16; kk++) {
            const ulonglong2* ap = (const ulonglong2*)&As2[cur][kk * 66 + tm];
            const ulonglong2 a01 = ap[0];
            const ulonglong2 a23 = ap[1];
            const ulonglong2 a45 = ap[2];
            const ulonglong2 a67 = ap[3];
            W4 w;
            w.v = *(const float4*)&Ws[cur][kk][tn];
            FMA2(acc2[0][0], a01.x, w.u[0]); FMA2(acc2[0][1], a01.x, w.u[1]);
            FMA2(acc2[1][0], a01.y, w.u[0]); FMA2(acc2[1][1], a01.y, w.u[1]);
            FMA2(acc2[2][0], a23.x, w.u[0]); FMA2(acc2[2][1], a23.x, w.u[1]);
            FMA2(acc2[3][0], a23.y, w.u[0]); FMA2(acc2[3][1], a23.y, w.u[1]);
            FMA2(acc2[4][0], a45.x, w.u[0]); FMA2(acc2[4][1], a45.x, w.u[1]);
            FMA2(acc2[5][0], a45.y, w.u[0]); FMA2(acc2[5][1], a45.y, w.u[1]);
            FMA2(acc2[6][0], a67.x, w.u[0]); FMA2(acc2[6][1], a67.x, w.u[1]);
            FMA2(acc2[7][0], a67.y, w.u[0]); FMA2(acc2[7][1], a67.y, w.u[1]);
        }
        if (more) STORE(cur ^ 1, va, vw0, vw1);
        __syncthreads();
    }

    // ---------------- epilogue: (accum), bias, store, fused BN stats ----------------
    const float bb0 = bias ? bias[tn]     : 0.f;
    const float bb1 = bias ? bias[tn + 1] : 0.f;
    const float bb2 = bias ? bias[tn + 2] : 0.f;
    const float bb3 = bias ? bias[tn + 3] : 0.f;
    float psum[4] = {0.f, 0.f, 0.f, 0.f};
    float psq[4]  = {0.f, 0.f, 0.f, 0.f};
#pragma unroll
    for (int i = 0; i < 8; i++) {
        const int r = row0 + tm + i;
        if (r < Nn) {
            F2 p0, p1;
            p0.u = acc2[i][0];
            p1.u = acc2[i][1];
            float4 o;
            o.x = p0.f.x + bb0; o.y = p0.f.y + bb1;
            o.z = p1.f.x + bb2; o.w = p1.f.y + bb3;
            if (accumC) {
                const float4 prev = *(const float4*)(C + (size_t)r * 128 + tn);
                o.x += prev.x; o.y += prev.y; o.z += prev.z; o.w += prev.w;
            }
            *(float4*)(C + (size_t)r * 128 + tn) = o;
            psum[0] += o.x; psum[1] += o.y; psum[2] += o.z; psum[3] += o.w;
            psq[0] += o.x * o.x; psq[1] += o.y * o.y;
            psq[2] += o.z * o.z; psq[3] += o.w * o.w;
        }
    }
    if (stats) {
#pragma unroll
        for (int j = 0; j < 4; j++) {
            atomicAdd(&sh_sum[tn + j], psum[j]);
            atomicAdd(&sh_sq[tn + j], psq[j]);
        }
        __syncthreads();
        if (tid < 128) {
            atomicAdd(&stats[tid], sh_sum[tid]);
            atomicAdd(&stats[128 + tid], sh_sq[tid]);
        }
    }
}

// ---------------- BN finalize ----------------
__global__ void finalize_kernel(const float* __restrict__ stats,
                                const float* __restrict__ gamma,
                                const float* __restrict__ beta,
                                float* __restrict__ bnp, float invN) {
    const int c = threadIdx.x;  // 128 threads
    const float mu   = stats[c] * invN;
    const float var  = stats[128 + c] * invN - mu * mu;
    const float rstd = rsqrtf(var + 1e-5f);
    const float sc   = rstd * gamma[c];
    bnp[c]       = sc;
    bnp[128 + c] = beta[c] - mu * sc;
}

// ---------------- out = relu(h1*scale + shift + r) ----------------
__global__ void final_kernel(const float4* __restrict__ h1, const float* __restrict__ bnp,
                             const float4* __restrict__ r, float4* __restrict__ out,
                             int total4) {
    const int i = blockIdx.x * blockDim.x + threadIdx.x;
    if (i >= total4) return;
    const int c = (i & 31) * 4;
    const float4 v = h1[i];
    const float4 rv = r[i];
    float4 o;
    o.x = fmaxf(fmaf(v.x, bnp[c + 0], bnp[128 + c + 0]) + rv.x, 0.f);
    o.y = fmaxf(fmaf(v.y, bnp[c + 1], bnp[128 + c + 1]) + rv.y, 0.f);
    o.z = fmaxf(fmaf(v.z, bnp[c + 2], bnp[128 + c + 2]) + rv.z, 0.f);
    o.w = fmaxf(fmaf(v.w, bnp[c + 3], bnp[128 + c + 3]) + rv.w, 0.f);
    out[i] = o;
}

// ---------------- launch (round-8 structure) ----------------
extern "C" void kernel_launch(void* const* d_in, const int* in_sizes, int n_in,
                              void* d_out, int out_size) {
    const float* x    = (const float*)d_in[0];
    const int*   ei   = (const int*)d_in[1];
    const float* Wr0  = (const float*)d_in[2];
    const float* Wn0  = (const float*)d_in[3];
    const float* b0   = (const float*)d_in[4];
    const float* g0   = (const float*)d_in[5];
    const float* be0  = (const float*)d_in[6];
    const float* Wr1  = (const float*)d_in[7];
    const float* Wn1  = (const float*)d_in[8];
    const float* b1   = (const float*)d_in[9];
    const float* g1   = (const float*)d_in[10];
    const float* be1  = (const float*)d_in[11];
    const float* Wlin = (const float*)d_in[12];
    const float* blin = (const float*)d_in[13];
    float* out = (float*)d_out;

    const int N = in_sizes[0] / CINn;
    const int E = in_sizes[1] / 2;
    const int* src = ei;
    const int* dst = ei + E;

    float *agg0, *agg1, *h0, *h1, *r, *stats, *bnp;
    int *deg, *lscan, *part, *rowptr, *cursor, *eidx;
    cudaGetSymbolAddress((void**)&agg0,   g_agg0);
    cudaGetSymbolAddress((void**)&agg1,   g_agg1);
    cudaGetSymbolAddress((void**)&h0,     g_h0);
    cudaGetSymbolAddress((void**)&h1,     g_h1);
    cudaGetSymbolAddress((void**)&r,      g_r);
    cudaGetSymbolAddress((void**)&stats,  g_stats);
    cudaGetSymbolAddress((void**)&bnp,    g_bnp);
    cudaGetSymbolAddress((void**)&deg,    g_deg);
    cudaGetSymbolAddress((void**)&lscan,  g_lscan);
    cudaGetSymbolAddress((void**)&part,   g_part);
    cudaGetSymbolAddress((void**)&rowptr, g_rowptr);
    cudaGetSymbolAddress((void**)&cursor, g_cursor);
    cudaGetSymbolAddress((void**)&eidx,   g_eidx);

    // side stream + fork/join events (created once)
    static cudaStream_t s2 = nullptr;
    static cudaEvent_t ev0 = nullptr, ev1 = nullptr, ev2 = nullptr, ev3 = nullptr;
    if (!s2) {
        cudaStreamCreate(&s2);
        cudaEventCreateWithFlags(&ev0, cudaEventDisableTiming);
        cudaEventCreateWithFlags(&ev1, cudaEventDisableTiming);
        cudaEventCreateWithFlags(&ev2, cudaEventDisableTiming);
        cudaEventCreateWithFlags(&ev3, cudaEventDisableTiming);
    }

    cudaMemsetAsync(deg,   0, (size_t)N * sizeof(int));
    cudaMemsetAsync(stats, 0, 4 * COUTn * sizeof(float));

    const int nb = (N + SCAN_B - 1) / SCAN_B;
    const int gemmBlocks = (N + 63) / 64;
    const int T4 = N * 32;

    // ---- fork: r = x @ Wlin^T + blin on side stream ----
    cudaEventRecord(ev0, 0);
    cudaStreamWaitEvent(s2, ev0, 0);
    gemm_kernel<<<gemmBlocks, 256, 0, s2>>>(x, Wlin, nullptr, nullptr, blin, r,
                                            nullptr, nullptr, N, CINn, 0);
    cudaEventRecord(ev1, s2);

    // ---- main: CSR build + layer-0 aggregation ----
    hist_kernel<<<(E + 255) / 256, 256>>>(dst, deg, E);
    scan1_kernel<<<nb, SCAN_B>>>(deg, lscan, part, N);
    scan2_kernel<<<1, 256>>>(part, nb);
    scan3_kernel<<<(N + 255) / 256, 256>>>(lscan, part, rowptr, cursor, N, E);
    fill_kernel<<<(E + 255) / 256, 256>>>(src, dst, cursor, eidx, E);
    gather0_kernel<<<(N + 15) / 16, 256>>>(rowptr, eidx, (const float4*)x,
                                           (float4*)agg0, N);

    // h0 = x @ Wr0^T + agg0 @ Wn0^T + b0 (+ fused BN stats)
    gemm_kernel<<<gemmBlocks, 256>>>(x, Wr0, agg0, Wn0, b0, h0,
                                     stats, nullptr, N, CINn, 0);
    finalize_kernel<<<1, 128>>>(stats, g0, be0, bnp, 1.0f / (float)N);

    // ---- fork: gather1 (needs h0, bnp) on side stream ----
    cudaEventRecord(ev2, 0);
    cudaStreamWaitEvent(s2, ev2, 0);
    gather1_kernel<<<(N + 7) / 8, 256, 0, s2>>>(rowptr, eidx, (const float4*)h0, bnp,
                                                (float4*)agg1, N);
    cudaEventRecord(ev3, s2);

    // ---- main (concurrent with gather1): h1 = relu(bn(h0)) @ Wr1^T + b1 ----
    gemm_kernel<<<gemmBlocks, 256>>>(h0, Wr1, nullptr, nullptr, b1, h1,
                                     nullptr, bnp, N, COUTn, 0);

    // ---- join, then h1 += agg1 @ Wn1^T (+ fused BN stats over final h1) ----
    cudaStreamWaitEvent(0, ev3, 0);
    gemm_kernel<<<gemmBlocks, 256>>>(agg1, Wn1, nullptr, nullptr, nullptr, h1,
                                     stats + 2 * COUTn, nullptr, N, COUTn, 1);
    finalize_kernel<<<1, 128>>>(stats + 2 * COUTn, g1, be1, bnp + 2 * COUTn, 1.0f / (float)N);

    // ---- join r, then out = relu(bn(h1) + r) ----
    cudaStreamWaitEvent(0, ev1, 0);
    final_kernel<<<(T4 + 255) / 256, 256>>>((const float4*)h1, bnp + 2 * COUTn,
                                            (const float4*)r, (float4*)out, T4);
}

// round 13
// speedup vs baseline: 1.0141x; 1.0141x over previous
#include <cuda_runtime.h>
#include <cstdint>

typedef unsigned long long ull;

// Problem constants (fixed shapes per reference)
#define NN    100000
#define EE    1600000
#define CINn  64
#define COUTn 128
#define SCAN_B 512

// ---------------- scratch (static device globals; no runtime alloc) ----------------
__device__ float g_agg0[(size_t)NN * CINn];
__device__ float g_agg1[(size_t)NN * COUTn];
__device__ float g_h0[(size_t)NN * COUTn];
__device__ float g_h1[(size_t)NN * COUTn];
__device__ float g_r[(size_t)NN * COUTn];
__device__ float g_stats[4 * COUTn];   // [sum0|sq0|sum1|sq1]
// CSR scratch
__device__ int g_deg[NN];
__device__ int g_lscan[NN];
__device__ int g_part[256];
__device__ int g_rowptr[NN + 1];
__device__ int g_cursor[NN];
__device__ int g_eidx[EE];

// ---------------- packed fp32x2 FMA ----------------
#define FMA2(acc, a, w) \
    asm("fma.rn.f32x2 %0, %1, %2, %0;" : "+l"(acc) : "l"(a), "l"(w))

__device__ __forceinline__ ull dup2(float f) {
    ull r;
    asm("mov.b64 %0, {%1, %1};" : "=l"(r) : "f"(f));
    return r;
}

union F2 { ull u; float2 f; };
union W4 { float4 v; ull u[2]; };

// compute BN scale/shift for channel c from raw sums
__device__ __forceinline__ float2 bn_coef(const float* stats, const float* gamma,
                                          const float* beta, float invN, int c) {
    const float mu  = stats[c] * invN;
    const float var = stats[128 + c] * invN - mu * mu;
    const float sc  = rsqrtf(var + 1e-5f) * gamma[c];
    return make_float2(sc, beta[c] - mu * sc);
}

// =============================================================================
// CSR build: histogram -> scan -> fill
// =============================================================================
__global__ void hist_kernel(const int* __restrict__ dst, int* __restrict__ deg, int E) {
    const int e = blockIdx.x * blockDim.x + threadIdx.x;
    if (e < E) atomicAdd(&deg[dst[e]], 1);
}

__global__ void scan1_kernel(const int* __restrict__ deg, int* __restrict__ lscan,
                             int* __restrict__ part, int N) {
    __shared__ int sh[SCAN_B];
    const int i = blockIdx.x * SCAN_B + threadIdx.x;
    const int v = (i < N) ? deg[i] : 0;
    sh[threadIdx.x] = v;
    __syncthreads();
#pragma unroll
    for (int off = 1; off < SCAN_B; off <<= 1) {
        int t = (threadIdx.x >= off) ? sh[threadIdx.x - off] : 0;
        __syncthreads();
        sh[threadIdx.x] += t;
        __syncthreads();
    }
    if (i < N) lscan[i] = sh[threadIdx.x] - v;
    if (threadIdx.x == SCAN_B - 1) part[blockIdx.x] = sh[threadIdx.x];
}

// scan3 with in-kernel partition prefix: each 256-thread block lies within one
// SCAN_B segment, so thread 0 sums part[0..seg) (nb <= 196) into smem.
__global__ void scan3_kernel(const int* __restrict__ lscan, const int* __restrict__ part,
                             int* __restrict__ rowptr, int* __restrict__ cursor,
                             int N, int E, int nb) {
    __shared__ int base;
    const int seg = (blockIdx.x * 256) / SCAN_B;
    if (threadIdx.x == 0) {
        int b = 0;
        for (int j = 0; j < seg; j++) b += part[j];
        base = b;
    }
    __syncthreads();
    const int i = blockIdx.x * 256 + threadIdx.x;
    if (i < N) {
        const int r = lscan[i] + base;
        rowptr[i] = r;
        cursor[i] = r;
    }
    if (i == 0) rowptr[N] = E;
}

__global__ void fill_kernel(const int* __restrict__ src, const int* __restrict__ dst,
                            int* __restrict__ cursor, int* __restrict__ eidx, int E) {
    const int e = blockIdx.x * blockDim.x + threadIdx.x;
    if (e < E) {
        const int pos = atomicAdd(&cursor[dst[e]], 1);
        eidx[pos] = src[e];
    }
}

// =============================================================================
// Gather (layer 0): agg0[n] = sum x[src], 4-edge unrolled, C4=16
// =============================================================================
__global__ void gather0_kernel(const int* __restrict__ rowptr, const int* __restrict__ eidx,
                               const float4* __restrict__ feat, float4* __restrict__ agg,
                               int N) {
    const int g = threadIdx.x >> 4;
    const int c = threadIdx.x & 15;
    const int node = blockIdx.x * 16 + g;
    if (node >= N) return;
    const int beg = rowptr[node];
    const int end = rowptr[node + 1];
    float4 acc = make_float4(0.f, 0.f, 0.f, 0.f);
    int e = beg;
    for (; e + 3 < end; e += 4) {
        const int s0 = eidx[e], s1 = eidx[e + 1], s2 = eidx[e + 2], s3 = eidx[e + 3];
        const float4 v0 = feat[(size_t)s0 * 16 + c];
        const float4 v1 = feat[(size_t)s1 * 16 + c];
        const float4 v2 = feat[(size_t)s2 * 16 + c];
        const float4 v3 = feat[(size_t)s3 * 16 + c];
        acc.x += v0.x + v1.x + v2.x + v3.x;
        acc.y += v0.y + v1.y + v2.y + v3.y;
        acc.z += v0.z + v1.z + v2.z + v3.z;
        acc.w += v0.w + v1.w + v2.w + v3.w;
    }
    for (; e < end; e++) {
        const int s = eidx[e];
        const float4 v = feat[(size_t)s * 16 + c];
        acc.x += v.x; acc.y += v.y; acc.z += v.z; acc.w += v.w;
    }
    agg[(size_t)node * 16 + c] = acc;
}

// =============================================================================
// Gather (layer 1) with fused bn+relu (bn coefs computed in-block from stats):
// agg1[n] = sum relu(bn(h0[src])), 4-edge unrolled, C4=32
// =============================================================================
__global__ void gather1_kernel(const int* __restrict__ rowptr, const int* __restrict__ eidx,
                               const float4* __restrict__ h0,
                               const float* __restrict__ stats,
                               const float* __restrict__ gamma,
                               const float* __restrict__ beta, float invN,
                               float4* __restrict__ agg, int N) {
    __shared__ float sbn[256];
    if (threadIdx.x < 128) {
        const float2 p = bn_coef(stats, gamma, beta, invN, threadIdx.x);
        sbn[threadIdx.x] = p.x;
        sbn[128 + threadIdx.x] = p.y;
    }
    __syncthreads();
    const int g = threadIdx.x >> 5;
    const int c = threadIdx.x & 31;
    const int node = blockIdx.x * 8 + g;
    if (node >= N) return;
    const float sc0 = sbn[c * 4 + 0], sh0 = sbn[128 + c * 4 + 0];
    const float sc1 = sbn[c * 4 + 1], sh1 = sbn[128 + c * 4 + 1];
    const float sc2 = sbn[c * 4 + 2], sh2 = sbn[128 + c * 4 + 2];
    const float sc3 = sbn[c * 4 + 3], sh3 = sbn[128 + c * 4 + 3];
    const int beg = rowptr[node];
    const int end = rowptr[node + 1];
    float4 acc = make_float4(0.f, 0.f, 0.f, 0.f);
    int e = beg;
    for (; e + 3 < end; e += 4) {
        const int s0 = eidx[e], s1 = eidx[e + 1], s2 = eidx[e + 2], s3 = eidx[e + 3];
        const float4 v0 = h0[(size_t)s0 * 32 + c];
        const float4 v1 = h0[(size_t)s1 * 32 + c];
        const float4 v2 = h0[(size_t)s2 * 32 + c];
        const float4 v3 = h0[(size_t)s3 * 32 + c];
        acc.x += fmaxf(fmaf(v0.x, sc0, sh0), 0.f) + fmaxf(fmaf(v1.x, sc0, sh0), 0.f)
               + fmaxf(fmaf(v2.x, sc0, sh0), 0.f) + fmaxf(fmaf(v3.x, sc0, sh0), 0.f);
        acc.y += fmaxf(fmaf(v0.y, sc1, sh1), 0.f) + fmaxf(fmaf(v1.y, sc1, sh1), 0.f)
               + fmaxf(fmaf(v2.y, sc1, sh1), 0.f) + fmaxf(fmaf(v3.y, sc1, sh1), 0.f);
        acc.z += fmaxf(fmaf(v0.z, sc2, sh2), 0.f) + fmaxf(fmaf(v1.z, sc2, sh2), 0.f)
               + fmaxf(fmaf(v2.z, sc2, sh2), 0.f) + fmaxf(fmaf(v3.z, sc2, sh2), 0.f);
        acc.w += fmaxf(fmaf(v0.w, sc3, sh3), 0.f) + fmaxf(fmaf(v1.w, sc3, sh3), 0.f)
               + fmaxf(fmaf(v2.w, sc3, sh3), 0.f) + fmaxf(fmaf(v3.w, sc3, sh3), 0.f);
    }
    for (; e < end; e++) {
        const int s = eidx[e];
        const float4 v = h0[(size_t)s * 32 + c];
        acc.x += fmaxf(fmaf(v.x, sc0, sh0), 0.f);
        acc.y += fmaxf(fmaf(v.y, sc1, sh1), 0.f);
        acc.z += fmaxf(fmaf(v.z, sc2, sh2), 0.f);
        acc.w += fmaxf(fmaf(v.w, sc3, sh3), 0.f);
    }
    agg[(size_t)node * 32 + c] = acc;
}

// =============================================================================
// Double-buffered fp32x2 GEMM: C = A@W1^T (+ B@W2^T) [+ C if accumC] + bias.
// BM=64, BN=128, BK=16, 256 threads. One sync per k-step; LDG prefetch.
// Optional fused BN stats out; optional bnStats in (relu(bn(A)) on mat 0,
// coefficients computed in-block from raw sums).
// =============================================================================
__global__ __launch_bounds__(256) void gemm_kernel(
    const float* __restrict__ A, const float* __restrict__ W1,
    const float* __restrict__ B, const float* __restrict__ W2,
    const float* __restrict__ bias, float* __restrict__ C,
    float* __restrict__ stats,
    const float* __restrict__ bnStats, const float* __restrict__ bnGamma,
    const float* __restrict__ bnBeta, float invN,
    int Nn, int K, int accumC) {

    __shared__ alignas(16) ull As2[2][16 * 66];   // 2 x 8448 B
    __shared__ alignas(16) float Ws[2][16][128];  // 2 x 8192 B
    __shared__ float sh_sum[128];
    __shared__ float sh_sq[128];
    __shared__ float sbn[256];

    const int tid  = threadIdx.x;
    const int row0 = blockIdx.x * 64;
    const int warp = tid >> 5;
    const int lane = tid & 31;
    const int tm   = warp * 8;   // 8 rows per thread
    const int tn   = lane * 4;   // 4 cols per thread

    if (stats && tid < 128) { sh_sum[tid] = 0.f; sh_sq[tid] = 0.f; }
    if (bnStats && tid < 128) {
        const float2 p = bn_coef(bnStats, bnGamma, bnBeta, invN, tid);
        sbn[tid] = p.x;
        sbn[128 + tid] = p.y;
    }
    __syncthreads();

    const int ksPerMat = K >> 4;
    const int totSteps = (B != nullptr) ? 2 * ksPerMat : ksPerMat;

    const int am  = tid >> 2;            // A row within tile
    const int akq = (tid & 3) * 4;       // A k-quad
    const int wn  = tid >> 1;            // W n within tile
    const int wkq = (tid & 1) * 8;       // W k-oct

    auto LOAD = [&](int s, float4& va, float4& vw0, float4& vw1) {
        const int mt = (s >= ksPerMat) ? 1 : 0;
        const int k0 = (s - mt * ksPerMat) << 4;
        const float* Ap = mt ? B : A;
        const float* Wp = mt ? W2 : W1;
        const int rr = row0 + am;
        va = make_float4(0.f, 0.f, 0.f, 0.f);
        if (rr < Nn) va = *(const float4*)(Ap + (size_t)rr * K + k0 + akq);
        if (bnStats && mt == 0) {
            const int cc = k0 + akq;
            va.x = fmaxf(fmaf(va.x, sbn[cc + 0], sbn[128 + cc + 0]), 0.f);
            va.y = fmaxf(fmaf(va.y, sbn[cc + 1], sbn[128 + cc + 1]), 0.f);
            va.z = fmaxf(fmaf(va.z, sbn[cc + 2], sbn[128 + cc + 2]), 0.f);
            va.w = fmaxf(fmaf(va.w, sbn[cc + 3], sbn[128 + cc + 3]), 0.f);
        }
        const float* wrow = Wp + (size_t)wn * K + k0 + wkq;
        vw0 = *(const float4*)(wrow);
        vw1 = *(const float4*)(wrow + 4);
    };
    auto STORE = [&](int b, const float4& va, const float4& vw0, const float4& vw1) {
        As2[b][(akq + 0) * 66 + am] = dup2(va.x);
        As2[b][(akq + 1) * 66 + am] = dup2(va.y);
        As2[b][(akq + 2) * 66 + am] = dup2(va.z);
        As2[b][(akq + 3) * 66 + am] = dup2(va.w);
        Ws[b][wkq + 0][wn] = vw0.x; Ws[b][wkq + 1][wn] = vw0.y;
        Ws[b][wkq + 2][wn] = vw0.z; Ws[b][wkq + 3][wn] = vw0.w;
        Ws[b][wkq + 4][wn] = vw1.x; Ws[b][wkq + 5][wn] = vw1.y;
        Ws[b][wkq + 6][wn] = vw1.z; Ws[b][wkq + 7][wn] = vw1.w;
    };

    ull acc2[8][2];
#pragma unroll
    for (int i = 0; i < 8; i++) { acc2[i][0] = 0ull; acc2[i][1] = 0ull; }

    // prologue
    {
        float4 va, vw0, vw1;
        LOAD(0, va, vw0, vw1);
        STORE(0, va, vw0, vw1);
    }
    __syncthreads();

    for (int s = 0; s < totSteps; s++) {
        const int cur = s & 1;
        float4 va, vw0, vw1;
        const bool more = (s + 1 < totSteps);
        if (more) LOAD(s + 1, va, vw0, vw1);   // LDG in flight during compute
#pragma unroll
        for (int kk = 0; kk < 16; kk++) {
            const ulonglong2* ap = (const ulonglong2*)&As2[cur][kk * 66 + tm];
            const ulonglong2 a01 = ap[0];
            const ulonglong2 a23 = ap[1];
            const ulonglong2 a45 = ap[2];
            const ulonglong2 a67 = ap[3];
            W4 w;
            w.v = *(const float4*)&Ws[cur][kk][tn];
            FMA2(acc2[0][0], a01.x, w.u[0]); FMA2(acc2[0][1], a01.x, w.u[1]);
            FMA2(acc2[1][0], a01.y, w.u[0]); FMA2(acc2[1][1], a01.y, w.u[1]);
            FMA2(acc2[2][0], a23.x, w.u[0]); FMA2(acc2[2][1], a23.x, w.u[1]);
            FMA2(acc2[3][0], a23.y, w.u[0]); FMA2(acc2[3][1], a23.y, w.u[1]);
            FMA2(acc2[4][0], a45.x, w.u[0]); FMA2(acc2[4][1], a45.x, w.u[1]);
            FMA2(acc2[5][0], a45.y, w.u[0]); FMA2(acc2[5][1], a45.y, w.u[1]);
            FMA2(acc2[6][0], a67.x, w.u[0]); FMA2(acc2[6][1], a67.x, w.u[1]);
            FMA2(acc2[7][0], a67.y, w.u[0]); FMA2(acc2[7][1], a67.y, w.u[1]);
        }
        if (more) STORE(cur ^ 1, va, vw0, vw1);
        __syncthreads();
    }

    // ---------------- epilogue: (accum), bias, store, fused BN stats ----------------
    const float bb0 = bias ? bias[tn]     : 0.f;
    const float bb1 = bias ? bias[tn + 1] : 0.f;
    const float bb2 = bias ? bias[tn + 2] : 0.f;
    const float bb3 = bias ? bias[tn + 3] : 0.f;
    float psum[4] = {0.f, 0.f, 0.f, 0.f};
    float psq[4]  = {0.f, 0.f, 0.f, 0.f};
#pragma unroll
    for (int i = 0; i < 8; i++) {
        const int r = row0 + tm + i;
        if (r < Nn) {
            F2 p0, p1;
            p0.u = acc2[i][0];
            p1.u = acc2[i][1];
            float4 o;
            o.x = p0.f.x + bb0; o.y = p0.f.y + bb1;
            o.z = p1.f.x + bb2; o.w = p1.f.y + bb3;
            if (accumC) {
                const float4 prev = *(const float4*)(C + (size_t)r * 128 + tn);
                o.x += prev.x; o.y += prev.y; o.z += prev.z; o.w += prev.w;
            }
            *(float4*)(C + (size_t)r * 128 + tn) = o;
            psum[0] += o.x; psum[1] += o.y; psum[2] += o.z; psum[3] += o.w;
            psq[0] += o.x * o.x; psq[1] += o.y * o.y;
            psq[2] += o.z * o.z; psq[3] += o.w * o.w;
        }
    }
    if (stats) {
#pragma unroll
        for (int j = 0; j < 4; j++) {
            atomicAdd(&sh_sum[tn + j], psum[j]);
            atomicAdd(&sh_sq[tn + j], psq[j]);
        }
        __syncthreads();
        if (tid < 128) {
            atomicAdd(&stats[tid], sh_sum[tid]);
            atomicAdd(&stats[128 + tid], sh_sq[tid]);
        }
    }
}

// ---------------- out = relu(bn1(h1) + r), bn coefs computed in-block ----------------
__global__ void final_kernel(const float4* __restrict__ h1,
                             const float* __restrict__ stats,
                             const float* __restrict__ gamma,
                             const float* __restrict__ beta, float invN,
                             const float4* __restrict__ r, float4* __restrict__ out,
                             int total4) {
    __shared__ float sbn[256];
    if (threadIdx.x < 128) {
        const float2 p = bn_coef(stats, gamma, beta, invN, threadIdx.x);
        sbn[threadIdx.x] = p.x;
        sbn[128 + threadIdx.x] = p.y;
    }
    __syncthreads();
    const int i = blockIdx.x * blockDim.x + threadIdx.x;
    if (i >= total4) return;
    const int c = (i & 31) * 4;
    const float4 v = h1[i];
    const float4 rv = r[i];
    float4 o;
    o.x = fmaxf(fmaf(v.x, sbn[c + 0], sbn[128 + c + 0]) + rv.x, 0.f);
    o.y = fmaxf(fmaf(v.y, sbn[c + 1], sbn[128 + c + 1]) + rv.y, 0.f);
    o.z = fmaxf(fmaf(v.z, sbn[c + 2], sbn[128 + c + 2]) + rv.z, 0.f);
    o.w = fmaxf(fmaf(v.w, sbn[c + 3], sbn[128 + c + 3]) + rv.w, 0.f);
    out[i] = o;
}

// ---------------- launch (round-8/11 structure, finalize/scan2 folded) ----------------
extern "C" void kernel_launch(void* const* d_in, const int* in_sizes, int n_in,
                              void* d_out, int out_size) {
    const float* x    = (const float*)d_in[0];
    const int*   ei   = (const int*)d_in[1];
    const float* Wr0  = (const float*)d_in[2];
    const float* Wn0  = (const float*)d_in[3];
    const float* b0   = (const float*)d_in[4];
    const float* g0   = (const float*)d_in[5];
    const float* be0  = (const float*)d_in[6];
    const float* Wr1  = (const float*)d_in[7];
    const float* Wn1  = (const float*)d_in[8];
    const float* b1   = (const float*)d_in[9];
    const float* g1   = (const float*)d_in[10];
    const float* be1  = (const float*)d_in[11];
    const float* Wlin = (const float*)d_in[12];
    const float* blin = (const float*)d_in[13];
    float* out = (float*)d_out;

    const int N = in_sizes[0] / CINn;
    const int E = in_sizes[1] / 2;
    const int* src = ei;
    const int* dst = ei + E;
    const float invN = 1.0f / (float)N;

    float *agg0, *agg1, *h0, *h1, *r, *stats;
    int *deg, *lscan, *part, *rowptr, *cursor, *eidx;
    cudaGetSymbolAddress((void**)&agg0,   g_agg0);
    cudaGetSymbolAddress((void**)&agg1,   g_agg1);
    cudaGetSymbolAddress((void**)&h0,     g_h0);
    cudaGetSymbolAddress((void**)&h1,     g_h1);
    cudaGetSymbolAddress((void**)&r,      g_r);
    cudaGetSymbolAddress((void**)&stats,  g_stats);
    cudaGetSymbolAddress((void**)&deg,    g_deg);
    cudaGetSymbolAddress((void**)&lscan,  g_lscan);
    cudaGetSymbolAddress((void**)&part,   g_part);
    cudaGetSymbolAddress((void**)&rowptr, g_rowptr);
    cudaGetSymbolAddress((void**)&cursor, g_cursor);
    cudaGetSymbolAddress((void**)&eidx,   g_eidx);

    // side stream + fork/join events (created once)
    static cudaStream_t s2 = nullptr;
    static cudaEvent_t ev0 = nullptr, ev1 = nullptr, ev2 = nullptr, ev3 = nullptr;
    if (!s2) {
        cudaStreamCreate(&s2);
        cudaEventCreateWithFlags(&ev0, cudaEventDisableTiming);
        cudaEventCreateWithFlags(&ev1, cudaEventDisableTiming);
        cudaEventCreateWithFlags(&ev2, cudaEventDisableTiming);
        cudaEventCreateWithFlags(&ev3, cudaEventDisableTiming);
    }

    cudaMemsetAsync(deg,   0, (size_t)N * sizeof(int));
    cudaMemsetAsync(stats, 0, 4 * COUTn * sizeof(float));

    const int nb = (N + SCAN_B - 1) / SCAN_B;
    const int gemmBlocks = (N + 63) / 64;
    const int T4 = N * 32;

    // ---- fork: r = x @ Wlin^T + blin on side stream ----
    cudaEventRecord(ev0, 0);
    cudaStreamWaitEvent(s2, ev0, 0);
    gemm_kernel<<<gemmBlocks, 256, 0, s2>>>(x, Wlin, nullptr, nullptr, blin, r,
                                            nullptr, nullptr, nullptr, nullptr, 0.f,
                                            N, CINn, 0);
    cudaEventRecord(ev1, s2);

    // ---- main: CSR build + layer-0 aggregation ----
    hist_kernel<<<(E + 255) / 256, 256>>>(dst, deg, E);
    scan1_kernel<<<nb, SCAN_B>>>(deg, lscan, part, N);
    scan3_kernel<<<(N + 255) / 256, 256>>>(lscan, part, rowptr, cursor, N, E, nb);
    fill_kernel<<<(E + 255) / 256, 256>>>(src, dst, cursor, eidx, E);
    gather0_kernel<<<(N + 15) / 16, 256>>>(rowptr, eidx, (const float4*)x,
                                           (float4*)agg0, N);

    // h0 = x @ Wr0^T + agg0 @ Wn0^T + b0 (+ fused BN stats -> stats[0:256])
    gemm_kernel<<<gemmBlocks, 256>>>(x, Wr0, agg0, Wn0, b0, h0,
                                     stats, nullptr, nullptr, nullptr, 0.f,
                                     N, CINn, 0);

    // ---- fork: gather1 (needs h0, stats0) on side stream ----
    cudaEventRecord(ev2, 0);
    cudaStreamWaitEvent(s2, ev2, 0);
    gather1_kernel<<<(N + 7) / 8, 256, 0, s2>>>(rowptr, eidx, (const float4*)h0,
                                                stats, g0, be0, invN,
                                                (float4*)agg1, N);
    cudaEventRecord(ev3, s2);

    // ---- main (concurrent with gather1): h1 = relu(bn0(h0)) @ Wr1^T + b1 ----
    gemm_kernel<<<gemmBlocks, 256>>>(h0, Wr1, nullptr, nullptr, b1, h1,
                                     nullptr, stats, g0, be0, invN,
                                     N, COUTn, 0);

    // ---- join, then h1 += agg1 @ Wn1^T (+ fused BN stats -> stats[256:512]) ----
    cudaStreamWaitEvent(0, ev3, 0);
    gemm_kernel<<<gemmBlocks, 256>>>(agg1, Wn1, nullptr, nullptr, nullptr, h1,
                                     stats + 2 * COUTn, nullptr, nullptr, nullptr, 0.f,
                                     N, COUTn, 1);

    // ---- join r, then out = relu(bn1(h1) + r) ----
    cudaStreamWaitEvent(0, ev1, 0);
    final_kernel<<<(T4 + 255) / 256, 256>>>((const float4*)h1,
                                            stats + 2 * COUTn, g1, be1, invN,
                                            (const float4*)r, (float4*)out, T4);
}

// round 14
// speedup vs baseline: 1.0142x; 1.0001x over previous
#include <cuda_runtime.h>
#include <cstdint>

typedef unsigned long long ull;

// Problem constants (fixed shapes per reference)
#define NN    100000
#define EE    1600000
#define CINn  64
#define COUTn 128
#define SCAN_B 512

// ---------------- scratch (static device globals; no runtime alloc) ----------------
__device__ float g_agg0[(size_t)NN * CINn];
__device__ float g_agg1[(size_t)NN * COUTn];
__device__ float g_h0[(size_t)NN * COUTn];
__device__ float g_h1[(size_t)NN * COUTn];
__device__ float g_r[(size_t)NN * COUTn];
__device__ float g_stats[4 * COUTn];   // [sum0|sq0|sum1|sq1]
// CSR scratch
__device__ int g_deg[NN];
__device__ int g_lscan[NN];
__device__ int g_part[256];
__device__ int g_rowptr[NN + 1];
__device__ int g_cursor[NN];
__device__ int g_eidx[EE];

// ---------------- packed fp32x2 FMA ----------------
#define FMA2(acc, a, w) \
    asm("fma.rn.f32x2 %0, %1, %2, %0;" : "+l"(acc) : "l"(a), "l"(w))

__device__ __forceinline__ ull dup2(float f) {
    ull r;
    asm("mov.b64 %0, {%1, %1};" : "=l"(r) : "f"(f));
    return r;
}

union F2 { ull u; float2 f; };
union W4 { float4 v; ull u[2]; };

// compute BN scale/shift for channel c from raw sums
__device__ __forceinline__ float2 bn_coef(const float* stats, const float* gamma,
                                          const float* beta, float invN, int c) {
    const float mu  = stats[c] * invN;
    const float var = stats[128 + c] * invN - mu * mu;
    const float sc  = rsqrtf(var + 1e-5f) * gamma[c];
    return make_float2(sc, beta[c] - mu * sc);
}

// =============================================================================
// CSR build: histogram -> scan -> fill
// =============================================================================
__global__ void hist_kernel(const int* __restrict__ dst, int* __restrict__ deg, int E) {
    const int e = blockIdx.x * blockDim.x + threadIdx.x;
    if (e < E) atomicAdd(&deg[dst[e]], 1);
}

__global__ void scan1_kernel(const int* __restrict__ deg, int* __restrict__ lscan,
                             int* __restrict__ part, int N) {
    __shared__ int sh[SCAN_B];
    const int i = blockIdx.x * SCAN_B + threadIdx.x;
    const int v = (i < N) ? deg[i] : 0;
    sh[threadIdx.x] = v;
    __syncthreads();
#pragma unroll
    for (int off = 1; off < SCAN_B; off <<= 1) {
        int t = (threadIdx.x >= off) ? sh[threadIdx.x - off] : 0;
        __syncthreads();
        sh[threadIdx.x] += t;
        __syncthreads();
    }
    if (i < N) lscan[i] = sh[threadIdx.x] - v;
    if (threadIdx.x == SCAN_B - 1) part[blockIdx.x] = sh[threadIdx.x];
}

// scan3: each 256-thread block lies within one SCAN_B segment; the partition
// base (sum of part[0..seg)) is computed with a PARALLEL 256-wide smem scan.
__global__ void scan3_kernel(const int* __restrict__ lscan, const int* __restrict__ part,
                             int* __restrict__ rowptr, int* __restrict__ cursor,
                             int N, int E, int nb) {
    __shared__ int sp[256];
    const int seg = (blockIdx.x * 256) / SCAN_B;
    const int v = (threadIdx.x < seg) ? part[threadIdx.x] : 0;   // seg <= nb <= 196
    sp[threadIdx.x] = v;
    __syncthreads();
#pragma unroll
    for (int off = 1; off < 256; off <<= 1) {
        int t = (threadIdx.x >= off) ? sp[threadIdx.x - off] : 0;
        __syncthreads();
        sp[threadIdx.x] += t;
        __syncthreads();
    }
    const int base = sp[255];   // = sum part[0..seg)
    const int i = blockIdx.x * 256 + threadIdx.x;
    if (i < N) {
        const int r = lscan[i] + base;
        rowptr[i] = r;
        cursor[i] = r;
    }
    if (i == 0) rowptr[N] = E;
}

__global__ void fill_kernel(const int* __restrict__ src, const int* __restrict__ dst,
                            int* __restrict__ cursor, int* __restrict__ eidx, int E) {
    const int e = blockIdx.x * blockDim.x + threadIdx.x;
    if (e < E) {
        const int pos = atomicAdd(&cursor[dst[e]], 1);
        eidx[pos] = src[e];
    }
}

// =============================================================================
// Gather (layer 0): agg0[n] = sum x[src], warp-per-node, C4=16.
// Lane split: eo = lane>>4 selects edge parity, c = lane&15 selects column.
// Halves combined with shfl_xor(16); lanes 0-15 write. 2-deep unroll (4 edges
// in flight per warp).
// =============================================================================
__global__ void gather0_kernel(const int* __restrict__ rowptr, const int* __restrict__ eidx,
                               const float4* __restrict__ feat, float4* __restrict__ agg,
                               int N) {
    const int g = threadIdx.x >> 5;
    const int lane = threadIdx.x & 31;
    const int node = blockIdx.x * 8 + g;
    if (node >= N) return;
    const int c  = lane & 15;
    const int eo = lane >> 4;
    const int beg = rowptr[node];
    const int end = rowptr[node + 1];
    float4 acc = make_float4(0.f, 0.f, 0.f, 0.f);
    int e = beg + eo;
    for (; e + 2 < end; e += 4) {          // this half processes e and e+2
        const int s0 = eidx[e];
        const int s1 = eidx[e + 2];
        const float4 v0 = feat[(size_t)s0 * 16 + c];
        const float4 v1 = feat[(size_t)s1 * 16 + c];
        acc.x += v0.x + v1.x; acc.y += v0.y + v1.y;
        acc.z += v0.z + v1.z; acc.w += v0.w + v1.w;
    }
    if (e < end) {
        const int s = eidx[e];
        const float4 v = feat[(size_t)s * 16 + c];
        acc.x += v.x; acc.y += v.y; acc.z += v.z; acc.w += v.w;
    }
    // combine the two edge-parity halves (same c in both halves)
    acc.x += __shfl_xor_sync(0xFFFFFFFF, acc.x, 16);
    acc.y += __shfl_xor_sync(0xFFFFFFFF, acc.y, 16);
    acc.z += __shfl_xor_sync(0xFFFFFFFF, acc.z, 16);
    acc.w += __shfl_xor_sync(0xFFFFFFFF, acc.w, 16);
    if (eo == 0) agg[(size_t)node * 16 + c] = acc;
}

// =============================================================================
// Gather (layer 1) with fused bn+relu (bn coefs computed in-block from stats):
// agg1[n] = sum relu(bn(h0[src])), 4-edge unrolled, C4=32
// =============================================================================
__global__ void gather1_kernel(const int* __restrict__ rowptr, const int* __restrict__ eidx,
                               const float4* __restrict__ h0,
                               const float* __restrict__ stats,
                               const float* __restrict__ gamma,
                               const float* __restrict__ beta, float invN,
                               float4* __restrict__ agg, int N) {
    __shared__ float sbn[256];
    if (threadIdx.x < 128) {
        const float2 p = bn_coef(stats, gamma, beta, invN, threadIdx.x);
        sbn[threadIdx.x] = p.x;
        sbn[128 + threadIdx.x] = p.y;
    }
    __syncthreads();
    const int g = threadIdx.x >> 5;
    const int c = threadIdx.x & 31;
    const int node = blockIdx.x * 8 + g;
    if (node >= N) return;
    const float sc0 = sbn[c * 4 + 0], sh0 = sbn[128 + c * 4 + 0];
    const float sc1 = sbn[c * 4 + 1], sh1 = sbn[128 + c * 4 + 1];
    const float sc2 = sbn[c * 4 + 2], sh2 = sbn[128 + c * 4 + 2];
    const float sc3 = sbn[c * 4 + 3], sh3 = sbn[128 + c * 4 + 3];
    const int beg = rowptr[node];
    const int end = rowptr[node + 1];
    float4 acc = make_float4(0.f, 0.f, 0.f, 0.f);
    int e = beg;
    for (; e + 3 < end; e += 4) {
        const int s0 = eidx[e], s1 = eidx[e + 1], s2 = eidx[e + 2], s3 = eidx[e + 3];
        const float4 v0 = h0[(size_t)s0 * 32 + c];
        const float4 v1 = h0[(size_t)s1 * 32 + c];
        const float4 v2 = h0[(size_t)s2 * 32 + c];
        const float4 v3 = h0[(size_t)s3 * 32 + c];
        acc.x += fmaxf(fmaf(v0.x, sc0, sh0), 0.f) + fmaxf(fmaf(v1.x, sc0, sh0), 0.f)
               + fmaxf(fmaf(v2.x, sc0, sh0), 0.f) + fmaxf(fmaf(v3.x, sc0, sh0), 0.f);
        acc.y += fmaxf(fmaf(v0.y, sc1, sh1), 0.f) + fmaxf(fmaf(v1.y, sc1, sh1), 0.f)
               + fmaxf(fmaf(v2.y, sc1, sh1), 0.f) + fmaxf(fmaf(v3.y, sc1, sh1), 0.f);
        acc.z += fmaxf(fmaf(v0.z, sc2, sh2), 0.f) + fmaxf(fmaf(v1.z, sc2, sh2), 0.f)
               + fmaxf(fmaf(v2.z, sc2, sh2), 0.f) + fmaxf(fmaf(v3.z, sc2, sh2), 0.f);
        acc.w += fmaxf(fmaf(v0.w, sc3, sh3), 0.f) + fmaxf(fmaf(v1.w, sc3, sh3), 0.f)
               + fmaxf(fmaf(v2.w, sc3, sh3), 0.f) + fmaxf(fmaf(v3.w, sc3, sh3), 0.f);
    }
    for (; e < end; e++) {
        const int s = eidx[e];
        const float4 v = h0[(size_t)s * 32 + c];
        acc.x += fmaxf(fmaf(v.x, sc0, sh0), 0.f);
        acc.y += fmaxf(fmaf(v.y, sc1, sh1), 0.f);
        acc.z += fmaxf(fmaf(v.z, sc2, sh2), 0.f);
        acc.w += fmaxf(fmaf(v.w, sc3, sh3), 0.f);
    }
    agg[(size_t)node * 32 + c] = acc;
}

// =============================================================================
// Double-buffered fp32x2 GEMM: C = A@W1^T (+ B@W2^T) [+ C if accumC] + bias.
// BM=64, BN=128, BK=16, 256 threads. One sync per k-step; LDG prefetch.
// Optional fused BN stats out; optional bnStats in (relu(bn(A)) on mat 0).
// =============================================================================
__global__ __launch_bounds__(256) void gemm_kernel(
    const float* __restrict__ A, const float* __restrict__ W1,
    const float* __restrict__ B, const float* __restrict__ W2,
    const float* __restrict__ bias, float* __restrict__ C,
    float* __restrict__ stats,
    const float* __restrict__ bnStats, const float* __restrict__ bnGamma,
    const float* __restrict__ bnBeta, float invN,
    int Nn, int K, int accumC) {

    __shared__ alignas(16) ull As2[2][16 * 66];   // 2 x 8448 B
    __shared__ alignas(16) float Ws[2][16][128];  // 2 x 8192 B
    __shared__ float sh_sum[128];
    __shared__ float sh_sq[128];
    __shared__ float sbn[256];

    const int tid  = threadIdx.x;
    const int row0 = blockIdx.x * 64;
    const int warp = tid >> 5;
    const int lane = tid & 31;
    const int tm   = warp * 8;   // 8 rows per thread
    const int tn   = lane * 4;   // 4 cols per thread

    if (stats && tid < 128) { sh_sum[tid] = 0.f; sh_sq[tid] = 0.f; }
    if (bnStats && tid < 128) {
        const float2 p = bn_coef(bnStats, bnGamma, bnBeta, invN, tid);
        sbn[tid] = p.x;
        sbn[128 + tid] = p.y;
    }
    __syncthreads();

    const int ksPerMat = K >> 4;
    const int totSteps = (B != nullptr) ? 2 * ksPerMat : ksPerMat;

    const int am  = tid >> 2;            // A row within tile
    const int akq = (tid & 3) * 4;       // A k-quad
    const int wn  = tid >> 1;            // W n within tile
    const int wkq = (tid & 1) * 8;       // W k-oct

    auto LOAD = [&](int s, float4& va, float4& vw0, float4& vw1) {
        const int mt = (s >= ksPerMat) ? 1 : 0;
        const int k0 = (s - mt * ksPerMat) << 4;
        const float* Ap = mt ? B : A;
        const float* Wp = mt ? W2 : W1;
        const int rr = row0 + am;
        va = make_float4(0.f, 0.f, 0.f, 0.f);
        if (rr < Nn) va = *(const float4*)(Ap + (size_t)rr * K + k0 + akq);
        if (bnStats && mt == 0) {
            const int cc = k0 + akq;
            va.x = fmaxf(fmaf(va.x, sbn[cc + 0], sbn[128 + cc + 0]), 0.f);
            va.y = fmaxf(fmaf(va.y, sbn[cc + 1], sbn[128 + cc + 1]), 0.f);
            va.z = fmaxf(fmaf(va.z, sbn[cc + 2], sbn[128 + cc + 2]), 0.f);
            va.w = fmaxf(fmaf(va.w, sbn[cc + 3], sbn[128 + cc + 3]), 0.f);
        }
        const float* wrow = Wp + (size_t)wn * K + k0 + wkq;
        vw0 = *(const float4*)(wrow);
        vw1 = *(const float4*)(wrow + 4);
    };
    auto STORE = [&](int b, const float4& va, const float4& vw0, const float4& vw1) {
        As2[b][(akq + 0) * 66 + am] = dup2(va.x);
        As2[b][(akq + 1) * 66 + am] = dup2(va.y);
        As2[b][(akq + 2) * 66 + am] = dup2(va.z);
        As2[b][(akq + 3) * 66 + am] = dup2(va.w);
        Ws[b][wkq + 0][wn] = vw0.x; Ws[b][wkq + 1][wn] = vw0.y;
        Ws[b][wkq + 2][wn] = vw0.z; Ws[b][wkq + 3][wn] = vw0.w;
        Ws[b][wkq + 4][wn] = vw1.x; Ws[b][wkq + 5][wn] = vw1.y;
        Ws[b][wkq + 6][wn] = vw1.z; Ws[b][wkq + 7][wn] = vw1.w;
    };

    ull acc2[8][2];
#pragma unroll
    for (int i = 0; i < 8; i++) { acc2[i][0] = 0ull; acc2[i][1] = 0ull; }

    // prologue
    {
        float4 va, vw0, vw1;
        LOAD(0, va, vw0, vw1);
        STORE(0, va, vw0, vw1);
    }
    __syncthreads();

    for (int s = 0; s < totSteps; s++) {
        const int cur = s & 1;
        float4 va, vw0, vw1;
        const bool more = (s + 1 < totSteps);
        if (more) LOAD(s + 1, va, vw0, vw1);   // LDG in flight during compute
#pragma unroll
        for (int kk = 0; kk < 16; kk++) {
            const ulonglong2* ap = (const ulonglong2*)&As2[cur][kk * 66 + tm];
            const ulonglong2 a01 = ap[0];
            const ulonglong2 a23 = ap[1];
            const ulonglong2 a45 = ap[2];
            const ulonglong2 a67 = ap[3];
            W4 w;
            w.v = *(const float4*)&Ws[cur][kk][tn];
            FMA2(acc2[0][0], a01.x, w.u[0]); FMA2(acc2[0][1], a01.x, w.u[1]);
            FMA2(acc2[1][0], a01.y, w.u[0]); FMA2(acc2[1][1], a01.y, w.u[1]);
            FMA2(acc2[2][0], a23.x, w.u[0]); FMA2(acc2[2][1], a23.x, w.u[1]);
            FMA2(acc2[3][0], a23.y, w.u[0]); FMA2(acc2[3][1], a23.y, w.u[1]);
            FMA2(acc2[4][0], a45.x, w.u[0]); FMA2(acc2[4][1], a45.x, w.u[1]);
            FMA2(acc2[5][0], a45.y, w.u[0]); FMA2(acc2[5][1], a45.y, w.u[1]);
            FMA2(acc2[6][0], a67.x, w.u[0]); FMA2(acc2[6][1], a67.x, w.u[1]);
            FMA2(acc2[7][0], a67.y, w.u[0]); FMA2(acc2[7][1], a67.y, w.u[1]);
        }
        if (more) STORE(cur ^ 1, va, vw0, vw1);
        __syncthreads();
    }

    // ---------------- epilogue: (accum), bias, store, fused BN stats ----------------
    const float bb0 = bias ? bias[tn]     : 0.f;
    const float bb1 = bias ? bias[tn + 1] : 0.f;
    const float bb2 = bias ? bias[tn + 2] : 0.f;
    const float bb3 = bias ? bias[tn + 3] : 0.f;
    float psum[4] = {0.f, 0.f, 0.f, 0.f};
    float psq[4]  = {0.f, 0.f, 0.f, 0.f};
#pragma unroll
    for (int i = 0; i < 8; i++) {
        const int r = row0 + tm + i;
        if (r < Nn) {
            F2 p0, p1;
            p0.u = acc2[i][0];
            p1.u = acc2[i][1];
            float4 o;
            o.x = p0.f.x + bb0; o.y = p0.f.y + bb1;
            o.z = p1.f.x + bb2; o.w = p1.f.y + bb3;
            if (accumC) {
                const float4 prev = *(const float4*)(C + (size_t)r * 128 + tn);
                o.x += prev.x; o.y += prev.y; o.z += prev.z; o.w += prev.w;
            }
            *(float4*)(C + (size_t)r * 128 + tn) = o;
            psum[0] += o.x; psum[1] += o.y; psum[2] += o.z; psum[3] += o.w;
            psq[0] += o.x * o.x; psq[1] += o.y * o.y;
            psq[2] += o.z * o.z; psq[3] += o.w * o.w;
        }
    }
    if (stats) {
#pragma unroll
        for (int j = 0; j < 4; j++) {
            atomicAdd(&sh_sum[tn + j], psum[j]);
            atomicAdd(&sh_sq[tn + j], psq[j]);
        }
        __syncthreads();
        if (tid < 128) {
            atomicAdd(&stats[tid], sh_sum[tid]);
            atomicAdd(&stats[128 + tid], sh_sq[tid]);
        }
    }
}

// ---------------- out = relu(bn1(h1) + r), bn coefs computed in-block ----------------
__global__ void final_kernel(const float4* __restrict__ h1,
                             const float* __restrict__ stats,
                             const float* __restrict__ gamma,
                             const float* __restrict__ beta, float invN,
                             const float4* __restrict__ r, float4* __restrict__ out,
                             int total4) {
    __shared__ float sbn[256];
    if (threadIdx.x < 128) {
        const float2 p = bn_coef(stats, gamma, beta, invN, threadIdx.x);
        sbn[threadIdx.x] = p.x;
        sbn[128 + threadIdx.x] = p.y;
    }
    __syncthreads();
    const int i = blockIdx.x * blockDim.x + threadIdx.x;
    if (i >= total4) return;
    const int c = (i & 31) * 4;
    const float4 v = h1[i];
    const float4 rv = r[i];
    float4 o;
    o.x = fmaxf(fmaf(v.x, sbn[c + 0], sbn[128 + c + 0]) + rv.x, 0.f);
    o.y = fmaxf(fmaf(v.y, sbn[c + 1], sbn[128 + c + 1]) + rv.y, 0.f);
    o.z = fmaxf(fmaf(v.z, sbn[c + 2], sbn[128 + c + 2]) + rv.z, 0.f);
    o.w = fmaxf(fmaf(v.w, sbn[c + 3], sbn[128 + c + 3]) + rv.w, 0.f);
    out[i] = o;
}

// ---------------- launch ----------------
extern "C" void kernel_launch(void* const* d_in, const int* in_sizes, int n_in,
                              void* d_out, int out_size) {
    const float* x    = (const float*)d_in[0];
    const int*   ei   = (const int*)d_in[1];
    const float* Wr0  = (const float*)d_in[2];
    const float* Wn0  = (const float*)d_in[3];
    const float* b0   = (const float*)d_in[4];
    const float* g0   = (const float*)d_in[5];
    const float* be0  = (const float*)d_in[6];
    const float* Wr1  = (const float*)d_in[7];
    const float* Wn1  = (const float*)d_in[8];
    const float* b1   = (const float*)d_in[9];
    const float* g1   = (const float*)d_in[10];
    const float* be1  = (const float*)d_in[11];
    const float* Wlin = (const float*)d_in[12];
    const float* blin = (const float*)d_in[13];
    float* out = (float*)d_out;

    const int N = in_sizes[0] / CINn;
    const int E = in_sizes[1] / 2;
    const int* src = ei;
    const int* dst = ei + E;
    const float invN = 1.0f / (float)N;

    float *agg0, *agg1, *h0, *h1, *r, *stats;
    int *deg, *lscan, *part, *rowptr, *cursor, *eidx;
    cudaGetSymbolAddress((void**)&agg0,   g_agg0);
    cudaGetSymbolAddress((void**)&agg1,   g_agg1);
    cudaGetSymbolAddress((void**)&h0,     g_h0);
    cudaGetSymbolAddress((void**)&h1,     g_h1);
    cudaGetSymbolAddress((void**)&r,      g_r);
    cudaGetSymbolAddress((void**)&stats,  g_stats);
    cudaGetSymbolAddress((void**)&deg,    g_deg);
    cudaGetSymbolAddress((void**)&lscan,  g_lscan);
    cudaGetSymbolAddress((void**)&part,   g_part);
    cudaGetSymbolAddress((void**)&rowptr, g_rowptr);
    cudaGetSymbolAddress((void**)&cursor, g_cursor);
    cudaGetSymbolAddress((void**)&eidx,   g_eidx);

    // side stream + fork/join events (created once)
    static cudaStream_t s2 = nullptr;
    static cudaEvent_t ev0 = nullptr, ev1 = nullptr, ev2 = nullptr, ev3 = nullptr;
    if (!s2) {
        cudaStreamCreate(&s2);
        cudaEventCreateWithFlags(&ev0, cudaEventDisableTiming);
        cudaEventCreateWithFlags(&ev1, cudaEventDisableTiming);
        cudaEventCreateWithFlags(&ev2, cudaEventDisableTiming);
        cudaEventCreateWithFlags(&ev3, cudaEventDisableTiming);
    }

    cudaMemsetAsync(deg,   0, (size_t)N * sizeof(int));
    cudaMemsetAsync(stats, 0, 4 * COUTn * sizeof(float));

    const int nb = (N + SCAN_B - 1) / SCAN_B;
    const int gemmBlocks = (N + 63) / 64;
    const int T4 = N * 32;

    // ---- fork: r = x @ Wlin^T + blin on side stream ----
    cudaEventRecord(ev0, 0);
    cudaStreamWaitEvent(s2, ev0, 0);
    gemm_kernel<<<gemmBlocks, 256, 0, s2>>>(x, Wlin, nullptr, nullptr, blin, r,
                                            nullptr, nullptr, nullptr, nullptr, 0.f,
                                            N, CINn, 0);
    cudaEventRecord(ev1, s2);

    // ---- main: CSR build + layer-0 aggregation ----
    hist_kernel<<<(E + 255) / 256, 256>>>(dst, deg, E);
    scan1_kernel<<<nb, SCAN_B>>>(deg, lscan, part, N);
    scan3_kernel<<<(N + 255) / 256, 256>>>(lscan, part, rowptr, cursor, N, E, nb);
    fill_kernel<<<(E + 255) / 256, 256>>>(src, dst, cursor, eidx, E);
    gather0_kernel<<<(N + 7) / 8, 256>>>(rowptr, eidx, (const float4*)x,
                                         (float4*)agg0, N);

    // h0 = x @ Wr0^T + agg0 @ Wn0^T + b0 (+ fused BN stats -> stats[0:256])
    gemm_kernel<<<gemmBlocks, 256>>>(x, Wr0, agg0, Wn0, b0, h0,
                                     stats, nullptr, nullptr, nullptr, 0.f,
                                     N, CINn, 0);

    // ---- fork: gather1 (needs h0, stats0) on side stream ----
    cudaEventRecord(ev2, 0);
    cudaStreamWaitEvent(s2, ev2, 0);
    gather1_kernel<<<(N + 7) / 8, 256, 0, s2>>>(rowptr, eidx, (const float4*)h0,
                                                stats, g0, be0, invN,
                                                (float4*)agg1, N);
    cudaEventRecord(ev3, s2);

    // ---- main (concurrent with gather1): h1 = relu(bn0(h0)) @ Wr1^T + b1 ----
    gemm_kernel<<<gemmBlocks, 256>>>(h0, Wr1, nullptr, nullptr, b1, h1,
                                     nullptr, stats, g0, be0, invN,
                                     N, COUTn, 0);

    // ---- join, then h1 += agg1 @ Wn1^T (+ fused BN stats -> stats[256:512]) ----
    cudaStreamWaitEvent(0, ev3, 0);
    gemm_kernel<<<gemmBlocks, 256>>>(agg1, Wn1, nullptr, nullptr, nullptr, h1,
                                     stats + 2 * COUTn, nullptr, nullptr, nullptr, 0.f,
                                     N, COUTn, 1);

    // ---- join r, then out = relu(bn1(h1) + r) ----
    cudaStreamWaitEvent(0, ev1, 0);
    final_kernel<<<(T4 + 255) / 256, 256>>>((const float4*)h1,
                                            stats + 2 * COUTn, g1, be1, invN,
                                            (const float4*)r, (float4*)out, T4);
}

// round 15
// speedup vs baseline: 1.0335x; 1.0190x over previous
#include <cuda_runtime.h>
#include <cuda_bf16.h>
#include <cstdint>

typedef unsigned long long ull;
typedef unsigned int u32;

// Problem constants (fixed shapes per reference)
#define NN    100000
#define EE    1600000
#define CINn  64
#define COUTn 128
#define SCAN_B 512

// ---------------- scratch (static device globals; no runtime alloc) ----------------
__device__ float g_agg0[(size_t)NN * CINn];
__device__ float g_agg1[(size_t)NN * COUTn];
__device__ float g_h0[(size_t)NN * COUTn];
__device__ float g_h1[(size_t)NN * COUTn];
__device__ float g_r[(size_t)NN * COUTn];
__device__ float g_stats[4 * COUTn];   // [sum0|sq0|sum1|sq1]
// bf16 hi/lo pre-split weights: wr1 at 0, wn1 at 32768 (each hi 16384 + lo 16384)
__device__ __nv_bfloat16 g_wb[65536];
// CSR scratch
__device__ int g_deg[NN];
__device__ int g_lscan[NN];
__device__ int g_part[256];
__device__ int g_rowptr[NN + 1];
__device__ int g_cursor[NN];
__device__ int g_eidx[EE];

// ---------------- packed fp32x2 FMA ----------------
#define FMA2(acc, a, w) \
    asm("fma.rn.f32x2 %0, %1, %2, %0;" : "+l"(acc) : "l"(a), "l"(w))

__device__ __forceinline__ ull dup2(float f) {
    ull r;
    asm("mov.b64 %0, {%1, %1};" : "=l"(r) : "f"(f));
    return r;
}

union F2 { ull u; float2 f; };
union W4 { float4 v; ull u[2]; };

// pack two fp32 -> bf16x2 (a -> low half, b -> high half)
__device__ __forceinline__ u32 bpack(float a, float b) {
    u32 r;
    asm("cvt.rn.bf16x2.f32 %0, %1, %2;" : "=r"(r) : "f"(b), "f"(a));
    return r;
}

// HMMA m16n8k16 bf16 -> fp32 (baseline PTX; fragment mapping verified in R4)
#define MMA_BF16(c, a, b)                                                     \
    asm volatile("mma.sync.aligned.m16n8k16.row.col.f32.bf16.bf16.f32 "       \
                 "{%0,%1,%2,%3}, {%4,%5,%6,%7}, {%8,%9}, {%0,%1,%2,%3};"      \
                 : "+f"((c)[0]), "+f"((c)[1]), "+f"((c)[2]), "+f"((c)[3])     \
                 : "r"((a)[0]), "r"((a)[1]), "r"((a)[2]), "r"((a)[3]),        \
                   "r"((b)[0]), "r"((b)[1]))

// compute BN scale/shift for channel c from raw sums
__device__ __forceinline__ float2 bn_coef(const float* stats, const float* gamma,
                                          const float* beta, float invN, int c) {
    const float mu  = stats[c] * invN;
    const float var = stats[128 + c] * invN - mu * mu;
    const float sc  = rsqrtf(var + 1e-5f) * gamma[c];
    return make_float2(sc, beta[c] - mu * sc);
}

// =============================================================================
// Weight prep: fp32 -> bf16 hi (out[0:n)) + bf16 lo (out[n:2n))
// =============================================================================
__global__ void wprep_kernel(const float* __restrict__ w, __nv_bfloat16* __restrict__ out,
                             int n) {
    const int i = blockIdx.x * blockDim.x + threadIdx.x;
    if (i >= n) return;
    const float v = w[i];
    const __nv_bfloat16 h = __float2bfloat16(v);
    out[i]     = h;
    out[n + i] = __float2bfloat16(v - __bfloat162float(h));
}

// =============================================================================
// CSR build: histogram -> scan -> fill
// =============================================================================
__global__ void hist_kernel(const int* __restrict__ dst, int* __restrict__ deg, int E) {
    const int e = blockIdx.x * blockDim.x + threadIdx.x;
    if (e < E) atomicAdd(&deg[dst[e]], 1);
}

__global__ void scan1_kernel(const int* __restrict__ deg, int* __restrict__ lscan,
                             int* __restrict__ part, int N) {
    __shared__ int sh[SCAN_B];
    const int i = blockIdx.x * SCAN_B + threadIdx.x;
    const int v = (i < N) ? deg[i] : 0;
    sh[threadIdx.x] = v;
    __syncthreads();
#pragma unroll
    for (int off = 1; off < SCAN_B; off <<= 1) {
        int t = (threadIdx.x >= off) ? sh[threadIdx.x - off] : 0;
        __syncthreads();
        sh[threadIdx.x] += t;
        __syncthreads();
    }
    if (i < N) lscan[i] = sh[threadIdx.x] - v;
    if (threadIdx.x == SCAN_B - 1) part[blockIdx.x] = sh[threadIdx.x];
}

__global__ void scan3_kernel(const int* __restrict__ lscan, const int* __restrict__ part,
                             int* __restrict__ rowptr, int* __restrict__ cursor,
                             int N, int E, int nb) {
    __shared__ int sp[256];
    const int seg = (blockIdx.x * 256) / SCAN_B;
    const int v = (threadIdx.x < seg) ? part[threadIdx.x] : 0;
    sp[threadIdx.x] = v;
    __syncthreads();
#pragma unroll
    for (int off = 1; off < 256; off <<= 1) {
        int t = (threadIdx.x >= off) ? sp[threadIdx.x - off] : 0;
        __syncthreads();
        sp[threadIdx.x] += t;
        __syncthreads();
    }
    const int base = sp[255];
    const int i = blockIdx.x * 256 + threadIdx.x;
    if (i < N) {
        const int r = lscan[i] + base;
        rowptr[i] = r;
        cursor[i] = r;
    }
    if (i == 0) rowptr[N] = E;
}

__global__ void fill_kernel(const int* __restrict__ src, const int* __restrict__ dst,
                            int* __restrict__ cursor, int* __restrict__ eidx, int E) {
    const int e = blockIdx.x * blockDim.x + threadIdx.x;
    if (e < E) {
        const int pos = atomicAdd(&cursor[dst[e]], 1);
        eidx[pos] = src[e];
    }
}

// =============================================================================
// Gather (layer 0): agg0[n] = sum x[src], warp-per-node, C4=16
// =============================================================================
__global__ void gather0_kernel(const int* __restrict__ rowptr, const int* __restrict__ eidx,
                               const float4* __restrict__ feat, float4* __restrict__ agg,
                               int N) {
    const int g = threadIdx.x >> 5;
    const int lane = threadIdx.x & 31;
    const int node = blockIdx.x * 8 + g;
    if (node >= N) return;
    const int c  = lane & 15;
    const int eo = lane >> 4;
    const int beg = rowptr[node];
    const int end = rowptr[node + 1];
    float4 acc = make_float4(0.f, 0.f, 0.f, 0.f);
    int e = beg + eo;
    for (; e + 2 < end; e += 4) {
        const int s0 = eidx[e];
        const int s1 = eidx[e + 2];
        const float4 v0 = feat[(size_t)s0 * 16 + c];
        const float4 v1 = feat[(size_t)s1 * 16 + c];
        acc.x += v0.x + v1.x; acc.y += v0.y + v1.y;
        acc.z += v0.z + v1.z; acc.w += v0.w + v1.w;
    }
    if (e < end) {
        const int s = eidx[e];
        const float4 v = feat[(size_t)s * 16 + c];
        acc.x += v.x; acc.y += v.y; acc.z += v.z; acc.w += v.w;
    }
    acc.x += __shfl_xor_sync(0xFFFFFFFF, acc.x, 16);
    acc.y += __shfl_xor_sync(0xFFFFFFFF, acc.y, 16);
    acc.z += __shfl_xor_sync(0xFFFFFFFF, acc.z, 16);
    acc.w += __shfl_xor_sync(0xFFFFFFFF, acc.w, 16);
    if (eo == 0) agg[(size_t)node * 16 + c] = acc;
}

// =============================================================================
// Gather (layer 1) with fused bn+relu: agg1[n] = sum relu(bn(h0[src])), C4=32
// =============================================================================
__global__ void gather1_kernel(const int* __restrict__ rowptr, const int* __restrict__ eidx,
                               const float4* __restrict__ h0,
                               const float* __restrict__ stats,
                               const float* __restrict__ gamma,
                               const float* __restrict__ beta, float invN,
                               float4* __restrict__ agg, int N) {
    __shared__ float sbn[256];
    if (threadIdx.x < 128) {
        const float2 p = bn_coef(stats, gamma, beta, invN, threadIdx.x);
        sbn[threadIdx.x] = p.x;
        sbn[128 + threadIdx.x] = p.y;
    }
    __syncthreads();
    const int g = threadIdx.x >> 5;
    const int c = threadIdx.x & 31;
    const int node = blockIdx.x * 8 + g;
    if (node >= N) return;
    const float sc0 = sbn[c * 4 + 0], sh0 = sbn[128 + c * 4 + 0];
    const float sc1 = sbn[c * 4 + 1], sh1 = sbn[128 + c * 4 + 1];
    const float sc2 = sbn[c * 4 + 2], sh2 = sbn[128 + c * 4 + 2];
    const float sc3 = sbn[c * 4 + 3], sh3 = sbn[128 + c * 4 + 3];
    const int beg = rowptr[node];
    const int end = rowptr[node + 1];
    float4 acc = make_float4(0.f, 0.f, 0.f, 0.f);
    int e = beg;
    for (; e + 3 < end; e += 4) {
        const int s0 = eidx[e], s1 = eidx[e + 1], s2 = eidx[e + 2], s3 = eidx[e + 3];
        const float4 v0 = h0[(size_t)s0 * 32 + c];
        const float4 v1 = h0[(size_t)s1 * 32 + c];
        const float4 v2 = h0[(size_t)s2 * 32 + c];
        const float4 v3 = h0[(size_t)s3 * 32 + c];
        acc.x += fmaxf(fmaf(v0.x, sc0, sh0), 0.f) + fmaxf(fmaf(v1.x, sc0, sh0), 0.f)
               + fmaxf(fmaf(v2.x, sc0, sh0), 0.f) + fmaxf(fmaf(v3.x, sc0, sh0), 0.f);
        acc.y += fmaxf(fmaf(v0.y, sc1, sh1), 0.f) + fmaxf(fmaf(v1.y, sc1, sh1), 0.f)
               + fmaxf(fmaf(v2.y, sc1, sh1), 0.f) + fmaxf(fmaf(v3.y, sc1, sh1), 0.f);
        acc.z += fmaxf(fmaf(v0.z, sc2, sh2), 0.f) + fmaxf(fmaf(v1.z, sc2, sh2), 0.f)
               + fmaxf(fmaf(v2.z, sc2, sh2), 0.f) + fmaxf(fmaf(v3.z, sc2, sh2), 0.f);
        acc.w += fmaxf(fmaf(v0.w, sc3, sh3), 0.f) + fmaxf(fmaf(v1.w, sc3, sh3), 0.f)
               + fmaxf(fmaf(v2.w, sc3, sh3), 0.f) + fmaxf(fmaf(v3.w, sc3, sh3), 0.f);
    }
    for (; e < end; e++) {
        const int s = eidx[e];
        const float4 v = h0[(size_t)s * 32 + c];
        acc.x += fmaxf(fmaf(v.x, sc0, sh0), 0.f);
        acc.y += fmaxf(fmaf(v.y, sc1, sh1), 0.f);
        acc.z += fmaxf(fmaf(v.z, sc2, sh2), 0.f);
        acc.w += fmaxf(fmaf(v.w, sc3, sh3), 0.f);
    }
    agg[(size_t)node * 32 + c] = acc;
}

// =============================================================================
// FFMA GEMM (unchanged; used for r and layer-0): C = A@W1^T (+ B@W2^T) + bias.
// =============================================================================
__global__ __launch_bounds__(256) void gemm_kernel(
    const float* __restrict__ A, const float* __restrict__ W1,
    const float* __restrict__ B, const float* __restrict__ W2,
    const float* __restrict__ bias, float* __restrict__ C,
    float* __restrict__ stats,
    int Nn, int K) {

    __shared__ alignas(16) ull As2[2][16 * 66];
    __shared__ alignas(16) float Ws[2][16][128];
    __shared__ float sh_sum[128];
    __shared__ float sh_sq[128];

    const int tid  = threadIdx.x;
    const int row0 = blockIdx.x * 64;
    const int warp = tid >> 5;
    const int lane = tid & 31;
    const int tm   = warp * 8;
    const int tn   = lane * 4;

    if (stats && tid < 128) { sh_sum[tid] = 0.f; sh_sq[tid] = 0.f; }
    __syncthreads();

    const int ksPerMat = K >> 4;
    const int totSteps = (B != nullptr) ? 2 * ksPerMat : ksPerMat;

    const int am  = tid >> 2;
    const int akq = (tid & 3) * 4;
    const int wn  = tid >> 1;
    const int wkq = (tid & 1) * 8;

    auto LOAD = [&](int s, float4& va, float4& vw0, float4& vw1) {
        const int mt = (s >= ksPerMat) ? 1 : 0;
        const int k0 = (s - mt * ksPerMat) << 4;
        const float* Ap = mt ? B : A;
        const float* Wp = mt ? W2 : W1;
        const int rr = row0 + am;
        va = make_float4(0.f, 0.f, 0.f, 0.f);
        if (rr < Nn) va = *(const float4*)(Ap + (size_t)rr * K + k0 + akq);
        const float* wrow = Wp + (size_t)wn * K + k0 + wkq;
        vw0 = *(const float4*)(wrow);
        vw1 = *(const float4*)(wrow + 4);
    };
    auto STORE = [&](int b, const float4& va, const float4& vw0, const float4& vw1) {
        As2[b][(akq + 0) * 66 + am] = dup2(va.x);
        As2[b][(akq + 1) * 66 + am] = dup2(va.y);
        As2[b][(akq + 2) * 66 + am] = dup2(va.z);
        As2[b][(akq + 3) * 66 + am] = dup2(va.w);
        Ws[b][wkq + 0][wn] = vw0.x; Ws[b][wkq + 1][wn] = vw0.y;
        Ws[b][wkq + 2][wn] = vw0.z; Ws[b][wkq + 3][wn] = vw0.w;
        Ws[b][wkq + 4][wn] = vw1.x; Ws[b][wkq + 5][wn] = vw1.y;
        Ws[b][wkq + 6][wn] = vw1.z; Ws[b][wkq + 7][wn] = vw1.w;
    };

    ull acc2[8][2];
#pragma unroll
    for (int i = 0; i < 8; i++) { acc2[i][0] = 0ull; acc2[i][1] = 0ull; }

    {
        float4 va, vw0, vw1;
        LOAD(0, va, vw0, vw1);
        STORE(0, va, vw0, vw1);
    }
    __syncthreads();

    for (int s = 0; s < totSteps; s++) {
        const int cur = s & 1;
        float4 va, vw0, vw1;
        const bool more = (s + 1 < totSteps);
        if (more) LOAD(s + 1, va, vw0, vw1);
#pragma unroll
        for (int kk = 0; kk < 16; kk++) {
            const ulonglong2* ap = (const ulonglong2*)&As2[cur][kk * 66 + tm];
            const ulonglong2 a01 = ap[0];
            const ulonglong2 a23 = ap[1];
            const ulonglong2 a45 = ap[2];
            const ulonglong2 a67 = ap[3];
            W4 w;
            w.v = *(const float4*)&Ws[cur][kk][tn];
            FMA2(acc2[0][0], a01.x, w.u[0]); FMA2(acc2[0][1], a01.x, w.u[1]);
            FMA2(acc2[1][0], a01.y, w.u[0]); FMA2(acc2[1][1], a01.y, w.u[1]);
            FMA2(acc2[2][0], a23.x, w.u[0]); FMA2(acc2[2][1], a23.x, w.u[1]);
            FMA2(acc2[3][0], a23.y, w.u[0]); FMA2(acc2[3][1], a23.y, w.u[1]);
            FMA2(acc2[4][0], a45.x, w.u[0]); FMA2(acc2[4][1], a45.x, w.u[1]);
            FMA2(acc2[5][0], a45.y, w.u[0]); FMA2(acc2[5][1], a45.y, w.u[1]);
            FMA2(acc2[6][0], a67.x, w.u[0]); FMA2(acc2[6][1], a67.x, w.u[1]);
            FMA2(acc2[7][0], a67.y, w.u[0]); FMA2(acc2[7][1], a67.y, w.u[1]);
        }
        if (more) STORE(cur ^ 1, va, vw0, vw1);
        __syncthreads();
    }

    const float bb0 = bias ? bias[tn]     : 0.f;
    const float bb1 = bias ? bias[tn + 1] : 0.f;
    const float bb2 = bias ? bias[tn + 2] : 0.f;
    const float bb3 = bias ? bias[tn + 3] : 0.f;
    float psum[4] = {0.f, 0.f, 0.f, 0.f};
    float psq[4]  = {0.f, 0.f, 0.f, 0.f};
#pragma unroll
    for (int i = 0; i < 8; i++) {
        const int r = row0 + tm + i;
        if (r < Nn) {
            F2 p0, p1;
            p0.u = acc2[i][0];
            p1.u = acc2[i][1];
            float4 o;
            o.x = p0.f.x + bb0; o.y = p0.f.y + bb1;
            o.z = p1.f.x + bb2; o.w = p1.f.y + bb3;
            *(float4*)(C + (size_t)r * 128 + tn) = o;
            psum[0] += o.x; psum[1] += o.y; psum[2] += o.z; psum[3] += o.w;
            psq[0] += o.x * o.x; psq[1] += o.y * o.y;
            psq[2] += o.z * o.z; psq[3] += o.w * o.w;
        }
    }
    if (stats) {
#pragma unroll
        for (int j = 0; j < 4; j++) {
            atomicAdd(&sh_sum[tn + j], psum[j]);
            atomicAdd(&sh_sq[tn + j], psq[j]);
        }
        __syncthreads();
        if (tid < 128) {
            atomicAdd(&stats[tid], sh_sum[tid]);
            atomicAdd(&stats[128 + tid], sh_sq[tid]);
        }
    }
}

// =============================================================================
// Pipelined HMMA GEMM (K=128 fixed): C = f(A) @ W^T [+ C if accumC] [+ bias].
// f = relu(bn(.)) if bnStats else identity. 3-term bf16 split (Ah@Wh + Ah@Wl +
// Al@Wh), W pre-split hi/lo in Whl. CTA 128x128, 8 warps (2x4), BK=32, double-
// buffered smem (2 x 40KB), LDG prefetch + STS-after-compute, 1 sync/chunk.
// Fragment mapping identical to the R4-verified kernel (smem stride 40 bf16).
// =============================================================================
__global__ __launch_bounds__(256) void hmma_kernel(
    const float* __restrict__ A, const __nv_bfloat16* __restrict__ Whl,
    const float* __restrict__ bias, float* __restrict__ C,
    float* __restrict__ stats, const float* __restrict__ bnStats,
    const float* __restrict__ gamma, const float* __restrict__ beta, float invN,
    int Nn, int accumC) {

    extern __shared__ char dsm[];
    __shared__ float sh_sum[128];
    __shared__ float sh_sq[128];
    __shared__ float sbn[256];

    const int tid  = threadIdx.x;
    const int lane = tid & 31, wid = tid >> 5;
    const int g = lane >> 2, t = lane & 3;
    const int mrow = (wid >> 2) * 64;
    const int ncol = (wid & 3) * 32;
    const int row0 = blockIdx.x * 128;

    if (stats && tid < 128) { sh_sum[tid] = 0.f; sh_sq[tid] = 0.f; }
    if (bnStats && tid < 128) {
        const float2 p = bn_coef(bnStats, gamma, beta, invN, tid);
        sbn[tid] = p.x;
        sbn[128 + tid] = p.y;
    }
    __syncthreads();

    const __nv_bfloat16* Whi = Whl;
    const __nv_bfloat16* Wlo = Whl + 128 * 128;

    float acc[4][4][4];
#pragma unroll
    for (int a = 0; a < 4; a++)
#pragma unroll
        for (int b = 0; b < 4; b++)
#pragma unroll
            for (int c = 0; c < 4; c++) acc[a][b][c] = 0.f;

    // per-thread staging coords: idx = tid + p*256 -> row = idx>>3, kq = (idx&7)*4
    auto LDGC = [&](int kc, float4* ar, uint2* whr, uint2* wlr) {
#pragma unroll
        for (int p = 0; p < 4; p++) {
            const int idx = tid + p * 256;
            const int row = idx >> 3;
            const int kq  = (idx & 7) * 4;
            const int gr  = row0 + row;
            float4 v = make_float4(0.f, 0.f, 0.f, 0.f);
            if (gr < Nn) v = *(const float4*)(A + (size_t)gr * 128 + kc * 32 + kq);
            if (bnStats) {
                const int cc = kc * 32 + kq;
                v.x = fmaxf(fmaf(v.x, sbn[cc + 0], sbn[128 + cc + 0]), 0.f);
                v.y = fmaxf(fmaf(v.y, sbn[cc + 1], sbn[128 + cc + 1]), 0.f);
                v.z = fmaxf(fmaf(v.z, sbn[cc + 2], sbn[128 + cc + 2]), 0.f);
                v.w = fmaxf(fmaf(v.w, sbn[cc + 3], sbn[128 + cc + 3]), 0.f);
            }
            ar[p] = v;
            const size_t wo = (size_t)row * 128 + kc * 32 + kq;
            whr[p] = *(const uint2*)(Whi + wo);
            wlr[p] = *(const uint2*)(Wlo + wo);
        }
    };
    auto STSC = [&](int b, const float4* ar, const uint2* whr, const uint2* wlr) {
        char* base = dsm + b * 40960;
        __nv_bfloat16* pAh = (__nv_bfloat16*)(base);
        __nv_bfloat16* pAl = (__nv_bfloat16*)(base + 10240);
        __nv_bfloat16* pWh = (__nv_bfloat16*)(base + 20480);
        __nv_bfloat16* pWl = (__nv_bfloat16*)(base + 30720);
#pragma unroll
        for (int p = 0; p < 4; p++) {
            const int idx = tid + p * 256;
            const int row = idx >> 3;
            const int kq  = (idx & 7) * 4;
            const int so  = row * 40 + kq;
            const float4 v = ar[p];
            const float hx = __bfloat162float(__float2bfloat16(v.x));
            const float hy = __bfloat162float(__float2bfloat16(v.y));
            const float hz = __bfloat162float(__float2bfloat16(v.z));
            const float hw = __bfloat162float(__float2bfloat16(v.w));
            *(uint2*)(pAh + so) = make_uint2(bpack(v.x, v.y), bpack(v.z, v.w));
            *(uint2*)(pAl + so) = make_uint2(bpack(v.x - hx, v.y - hy),
                                             bpack(v.z - hz, v.w - hw));
            *(uint2*)(pWh + so) = whr[p];
            *(uint2*)(pWl + so) = wlr[p];
        }
    };
    auto COMPUTE = [&](int b) {
        char* base = dsm + b * 40960;
        const __nv_bfloat16* pAh = (const __nv_bfloat16*)(base);
        const __nv_bfloat16* pAl = (const __nv_bfloat16*)(base + 10240);
        const __nv_bfloat16* pWh = (const __nv_bfloat16*)(base + 20480);
        const __nv_bfloat16* pWl = (const __nv_bfloat16*)(base + 30720);
#pragma unroll
        for (int ks = 0; ks < 2; ks++) {
            const int k0 = ks * 16;
            u32 bh[4][2], bl[4][2];
#pragma unroll
            for (int nt = 0; nt < 4; nt++) {
                const int nb = (ncol + nt * 8 + g) * 40 + k0 + t * 2;
                bh[nt][0] = *(const u32*)(pWh + nb);
                bh[nt][1] = *(const u32*)(pWh + nb + 8);
                bl[nt][0] = *(const u32*)(pWl + nb);
                bl[nt][1] = *(const u32*)(pWl + nb + 8);
            }
#pragma unroll
            for (int mt = 0; mt < 4; mt++) {
                const int ab = (mrow + mt * 16 + g) * 40 + k0 + t * 2;
                u32 ah[4], al[4];
                ah[0] = *(const u32*)(pAh + ab);
                ah[1] = *(const u32*)(pAh + ab + 8 * 40);
                ah[2] = *(const u32*)(pAh + ab + 8);
                ah[3] = *(const u32*)(pAh + ab + 8 * 40 + 8);
                al[0] = *(const u32*)(pAl + ab);
                al[1] = *(const u32*)(pAl + ab + 8 * 40);
                al[2] = *(const u32*)(pAl + ab + 8);
                al[3] = *(const u32*)(pAl + ab + 8 * 40 + 8);
#pragma unroll
                for (int nt = 0; nt < 4; nt++) {
                    MMA_BF16(acc[mt][nt], ah, bh[nt]);
                    MMA_BF16(acc[mt][nt], ah, bl[nt]);
                    MMA_BF16(acc[mt][nt], al, bh[nt]);
                }
            }
        }
    };

    {
        float4 ar[4]; uint2 whr[4], wlr[4];
        LDGC(0, ar, whr, wlr);
        STSC(0, ar, whr, wlr);
    }
    __syncthreads();
    for (int c = 0; c < 4; c++) {
        float4 ar[4]; uint2 whr[4], wlr[4];
        const bool more = (c < 3);
        if (more) LDGC(c + 1, ar, whr, wlr);
        COMPUTE(c & 1);
        if (more) STSC((c + 1) & 1, ar, whr, wlr);
        __syncthreads();
    }

    // ---------------- epilogue: (accum), bias, store, fused BN stats ----------------
    float bcol[4][2];
#pragma unroll
    for (int nt = 0; nt < 4; nt++) {
        const int c = ncol + nt * 8 + t * 2;
        bcol[nt][0] = bias ? __ldg(bias + c)     : 0.f;
        bcol[nt][1] = bias ? __ldg(bias + c + 1) : 0.f;
    }
    float psum[4][2] = {}, psq[4][2] = {};
#pragma unroll
    for (int mt = 0; mt < 4; mt++) {
        const int r0 = row0 + mrow + mt * 16 + g;
        const int r1 = r0 + 8;
#pragma unroll
        for (int nt = 0; nt < 4; nt++) {
            const int c = ncol + nt * 8 + t * 2;
            if (r0 < Nn) {
                float2 o;
                o.x = acc[mt][nt][0] + bcol[nt][0];
                o.y = acc[mt][nt][1] + bcol[nt][1];
                if (accumC) {
                    const float2 prev = *(const float2*)(C + (size_t)r0 * 128 + c);
                    o.x += prev.x; o.y += prev.y;
                }
                *(float2*)(C + (size_t)r0 * 128 + c) = o;
                psum[nt][0] += o.x; psum[nt][1] += o.y;
                psq[nt][0] += o.x * o.x; psq[nt][1] += o.y * o.y;
            }
            if (r1 < Nn) {
                float2 o;
                o.x = acc[mt][nt][2] + bcol[nt][0];
                o.y = acc[mt][nt][3] + bcol[nt][1];
                if (accumC) {
                    const float2 prev = *(const float2*)(C + (size_t)r1 * 128 + c);
                    o.x += prev.x; o.y += prev.y;
                }
                *(float2*)(C + (size_t)r1 * 128 + c) = o;
                psum[nt][0] += o.x; psum[nt][1] += o.y;
                psq[nt][0] += o.x * o.x; psq[nt][1] += o.y * o.y;
            }
        }
    }
    if (stats) {
#pragma unroll
        for (int nt = 0; nt < 4; nt++) {
            const int c = ncol + nt * 8 + t * 2;
            atomicAdd(&sh_sum[c], psum[nt][0]);
            atomicAdd(&sh_sum[c + 1], psum[nt][1]);
            atomicAdd(&sh_sq[c], psq[nt][0]);
            atomicAdd(&sh_sq[c + 1], psq[nt][1]);
        }
        __syncthreads();
        if (tid < 128) {
            atomicAdd(&stats[tid], sh_sum[tid]);
            atomicAdd(&stats[128 + tid], sh_sq[tid]);
        }
    }
}

// ---------------- out = relu(bn1(h1) + r), bn coefs computed in-block ----------------
__global__ void final_kernel(const float4* __restrict__ h1,
                             const float* __restrict__ stats,
                             const float* __restrict__ gamma,
                             const float* __restrict__ beta, float invN,
                             const float4* __restrict__ r, float4* __restrict__ out,
                             int total4) {
    __shared__ float sbn[256];
    if (threadIdx.x < 128) {
        const float2 p = bn_coef(stats, gamma, beta, invN, threadIdx.x);
        sbn[threadIdx.x] = p.x;
        sbn[128 + threadIdx.x] = p.y;
    }
    __syncthreads();
    const int i = blockIdx.x * blockDim.x + threadIdx.x;
    if (i >= total4) return;
    const int c = (i & 31) * 4;
    const float4 v = h1[i];
    const float4 rv = r[i];
    float4 o;
    o.x = fmaxf(fmaf(v.x, sbn[c + 0], sbn[128 + c + 0]) + rv.x, 0.f);
    o.y = fmaxf(fmaf(v.y, sbn[c + 1], sbn[128 + c + 1]) + rv.y, 0.f);
    o.z = fmaxf(fmaf(v.z, sbn[c + 2], sbn[128 + c + 2]) + rv.z, 0.f);
    o.w = fmaxf(fmaf(v.w, sbn[c + 3], sbn[128 + c + 3]) + rv.w, 0.f);
    out[i] = o;
}

// ---------------- launch ----------------
extern "C" void kernel_launch(void* const* d_in, const int* in_sizes, int n_in,
                              void* d_out, int out_size) {
    const float* x    = (const float*)d_in[0];
    const int*   ei   = (const int*)d_in[1];
    const float* Wr0  = (const float*)d_in[2];
    const float* Wn0  = (const float*)d_in[3];
    const float* b0   = (const float*)d_in[4];
    const float* g0   = (const float*)d_in[5];
    const float* be0  = (const float*)d_in[6];
    const float* Wr1  = (const float*)d_in[7];
    const float* Wn1  = (const float*)d_in[8];
    const float* b1   = (const float*)d_in[9];
    const float* g1   = (const float*)d_in[10];
    const float* be1  = (const float*)d_in[11];
    const float* Wlin = (const float*)d_in[12];
    const float* blin = (const float*)d_in[13];
    float* out = (float*)d_out;

    const int N = in_sizes[0] / CINn;
    const int E = in_sizes[1] / 2;
    const int* src = ei;
    const int* dst = ei + E;
    const float invN = 1.0f / (float)N;

    float *agg0, *agg1, *h0, *h1, *r, *stats;
    __nv_bfloat16* wb;
    int *deg, *lscan, *part, *rowptr, *cursor, *eidx;
    cudaGetSymbolAddress((void**)&agg0,   g_agg0);
    cudaGetSymbolAddress((void**)&agg1,   g_agg1);
    cudaGetSymbolAddress((void**)&h0,     g_h0);
    cudaGetSymbolAddress((void**)&h1,     g_h1);
    cudaGetSymbolAddress((void**)&r,      g_r);
    cudaGetSymbolAddress((void**)&stats,  g_stats);
    cudaGetSymbolAddress((void**)&wb,     g_wb);
    cudaGetSymbolAddress((void**)&deg,    g_deg);
    cudaGetSymbolAddress((void**)&lscan,  g_lscan);
    cudaGetSymbolAddress((void**)&part,   g_part);
    cudaGetSymbolAddress((void**)&rowptr, g_rowptr);
    cudaGetSymbolAddress((void**)&cursor, g_cursor);
    cudaGetSymbolAddress((void**)&eidx,   g_eidx);

    cudaFuncSetAttribute(hmma_kernel, cudaFuncAttributeMaxDynamicSharedMemorySize, 81920);

    // side stream + fork/join events (created once)
    static cudaStream_t s2 = nullptr;
    static cudaEvent_t ev0 = nullptr, ev1 = nullptr, ev2 = nullptr, ev3 = nullptr;
    static cudaEvent_t evW = nullptr;
    if (!s2) {
        cudaStreamCreate(&s2);
        cudaEventCreateWithFlags(&ev0, cudaEventDisableTiming);
        cudaEventCreateWithFlags(&ev1, cudaEventDisableTiming);
        cudaEventCreateWithFlags(&ev2, cudaEventDisableTiming);
        cudaEventCreateWithFlags(&ev3, cudaEventDisableTiming);
        cudaEventCreateWithFlags(&evW, cudaEventDisableTiming);
    }

    cudaMemsetAsync(deg,   0, (size_t)N * sizeof(int));
    cudaMemsetAsync(stats, 0, 4 * COUTn * sizeof(float));

    const int nb = (N + SCAN_B - 1) / SCAN_B;
    const int gemmBlocks = (N + 63) / 64;
    const int hmmaBlocks = (N + 127) / 128;
    const int T4 = N * 32;

    // ---- fork on s2: weight prep (bf16 hi/lo) then r = x @ Wlin^T + blin ----
    cudaEventRecord(ev0, 0);
    cudaStreamWaitEvent(s2, ev0, 0);
    wprep_kernel<<<64, 256, 0, s2>>>(Wr1, wb, 128 * 128);
    wprep_kernel<<<64, 256, 0, s2>>>(Wn1, wb + 2 * 128 * 128, 128 * 128);
    cudaEventRecord(evW, s2);
    gemm_kernel<<<gemmBlocks, 256, 0, s2>>>(x, Wlin, nullptr, nullptr, blin, r,
                                            nullptr, N, CINn);
    cudaEventRecord(ev1, s2);

    // ---- main: CSR build + layer-0 aggregation ----
    hist_kernel<<<(E + 255) / 256, 256>>>(dst, deg, E);
    scan1_kernel<<<nb, SCAN_B>>>(deg, lscan, part, N);
    scan3_kernel<<<(N + 255) / 256, 256>>>(lscan, part, rowptr, cursor, N, E, nb);
    fill_kernel<<<(E + 255) / 256, 256>>>(src, dst, cursor, eidx, E);
    gather0_kernel<<<(N + 7) / 8, 256>>>(rowptr, eidx, (const float4*)x,
                                         (float4*)agg0, N);

    // h0 = x @ Wr0^T + agg0 @ Wn0^T + b0 (+ fused BN stats -> stats[0:256])
    gemm_kernel<<<gemmBlocks, 256>>>(x, Wr0, agg0, Wn0, b0, h0, stats, N, CINn);

    // ---- fork: gather1 (needs h0, stats0) on side stream ----
    cudaEventRecord(ev2, 0);
    cudaStreamWaitEvent(s2, ev2, 0);
    gather1_kernel<<<(N + 7) / 8, 256, 0, s2>>>(rowptr, eidx, (const float4*)h0,
                                                stats, g0, be0, invN,
                                                (float4*)agg1, N);
    cudaEventRecord(ev3, s2);

    // ---- main (concurrent with gather1): h1 = relu(bn0(h0)) @ Wr1^T + b1 (HMMA) ----
    cudaStreamWaitEvent(0, evW, 0);
    hmma_kernel<<<hmmaBlocks, 256, 81920>>>(h0, wb, b1, h1,
                                            nullptr, stats, g0, be0, invN, N, 0);

    // ---- join, then h1 += agg1 @ Wn1^T (HMMA, + fused BN stats -> stats[256:512]) ----
    cudaStreamWaitEvent(0, ev3, 0);
    hmma_kernel<<<hmmaBlocks, 256, 81920>>>(agg1, wb + 2 * 128 * 128, nullptr, h1,
                                            stats + 2 * COUTn, nullptr, nullptr, nullptr,
                                            0.f, N, 1);

    // ---- join r, then out = relu(bn1(h1) + r) ----
    cudaStreamWaitEvent(0, ev1, 0);
    final_kernel<<<(T4 + 255) / 256, 256>>>((const float4*)h1,
                                            stats + 2 * COUTn, g1, be1, invN,
                                            (const float4*)r, (float4*)out, T4);
}

// round 16
// speedup vs baseline: 1.0384x; 1.0047x over previous
#include <cuda_runtime.h>
#include <cuda_bf16.h>
#include <cstdint>

typedef unsigned long long ull;
typedef unsigned int u32;

// Problem constants (fixed shapes per reference)
#define NN    100000
#define EE    1600000
#define CINn  64
#define COUTn 128
#define SCAN_B 512

// ---------------- scratch (static device globals; no runtime alloc) ----------------
__device__ float g_agg0[(size_t)NN * CINn];
__device__ float g_agg1[(size_t)NN * COUTn];
__device__ float g_h0[(size_t)NN * COUTn];
__device__ float g_h1[(size_t)NN * COUTn];
__device__ float g_r[(size_t)NN * COUTn];
__device__ float g_stats[4 * COUTn];   // [sum0|sq0|sum1|sq1]
// bf16 hi/lo pre-split weights: wr1 at 0, wn1 at 32768 (each hi 16384 + lo 16384)
__device__ __nv_bfloat16 g_wb[65536];
// CSR scratch
__device__ int g_deg[NN];
__device__ int g_lscan[NN];
__device__ int g_part[256];
__device__ int g_rowptr[NN + 1];
__device__ int g_cursor[NN];
__device__ int g_eidx[EE];

// ---------------- packed fp32x2 FMA ----------------
#define FMA2(acc, a, w) \
    asm("fma.rn.f32x2 %0, %1, %2, %0;" : "+l"(acc) : "l"(a), "l"(w))

__device__ __forceinline__ ull dup2(float f) {
    ull r;
    asm("mov.b64 %0, {%1, %1};" : "=l"(r) : "f"(f));
    return r;
}

union F2 { ull u; float2 f; };
union W4 { float4 v; ull u[2]; };

// pack two fp32 -> bf16x2 (a -> low half, b -> high half)
__device__ __forceinline__ u32 bpack(float a, float b) {
    u32 r;
    asm("cvt.rn.bf16x2.f32 %0, %1, %2;" : "=r"(r) : "f"(b), "f"(a));
    return r;
}

// HMMA m16n8k16 bf16 -> fp32 (baseline PTX; fragment mapping verified)
#define MMA_BF16(c, a, b)                                                     \
    asm volatile("mma.sync.aligned.m16n8k16.row.col.f32.bf16.bf16.f32 "       \
                 "{%0,%1,%2,%3}, {%4,%5,%6,%7}, {%8,%9}, {%0,%1,%2,%3};"      \
                 : "+f"((c)[0]), "+f"((c)[1]), "+f"((c)[2]), "+f"((c)[3])     \
                 : "r"((a)[0]), "r"((a)[1]), "r"((a)[2]), "r"((a)[3]),        \
                   "r"((b)[0]), "r"((b)[1]))

// compute BN scale/shift for channel c from raw sums
__device__ __forceinline__ float2 bn_coef(const float* stats, const float* gamma,
                                          const float* beta, float invN, int c) {
    const float mu  = stats[c] * invN;
    const float var = stats[128 + c] * invN - mu * mu;
    const float sc  = rsqrtf(var + 1e-5f) * gamma[c];
    return make_float2(sc, beta[c] - mu * sc);
}

// =============================================================================
// Weight prep: fp32 -> bf16 hi (out[0:n)) + bf16 lo (out[n:2n))
// =============================================================================
__global__ void wprep_kernel(const float* __restrict__ w, __nv_bfloat16* __restrict__ out,
                             int n) {
    const int i = blockIdx.x * blockDim.x + threadIdx.x;
    if (i >= n) return;
    const float v = w[i];
    const __nv_bfloat16 h = __float2bfloat16(v);
    out[i]     = h;
    out[n + i] = __float2bfloat16(v - __bfloat162float(h));
}

// =============================================================================
// CSR build: histogram -> scan -> fill
// =============================================================================
__global__ void hist_kernel(const int* __restrict__ dst, int* __restrict__ deg, int E) {
    const int e = blockIdx.x * blockDim.x + threadIdx.x;
    if (e < E) atomicAdd(&deg[dst[e]], 1);
}

__global__ void scan1_kernel(const int* __restrict__ deg, int* __restrict__ lscan,
                             int* __restrict__ part, int N) {
    __shared__ int sh[SCAN_B];
    const int i = blockIdx.x * SCAN_B + threadIdx.x;
    const int v = (i < N) ? deg[i] : 0;
    sh[threadIdx.x] = v;
    __syncthreads();
#pragma unroll
    for (int off = 1; off < SCAN_B; off <<= 1) {
        int t = (threadIdx.x >= off) ? sh[threadIdx.x - off] : 0;
        __syncthreads();
        sh[threadIdx.x] += t;
        __syncthreads();
    }
    if (i < N) lscan[i] = sh[threadIdx.x] - v;
    if (threadIdx.x == SCAN_B - 1) part[blockIdx.x] = sh[threadIdx.x];
}

__global__ void scan3_kernel(const int* __restrict__ lscan, const int* __restrict__ part,
                             int* __restrict__ rowptr, int* __restrict__ cursor,
                             int N, int E, int nb) {
    __shared__ int sp[256];
    const int seg = (blockIdx.x * 256) / SCAN_B;
    const int v = (threadIdx.x < seg) ? part[threadIdx.x] : 0;
    sp[threadIdx.x] = v;
    __syncthreads();
#pragma unroll
    for (int off = 1; off < 256; off <<= 1) {
        int t = (threadIdx.x >= off) ? sp[threadIdx.x - off] : 0;
        __syncthreads();
        sp[threadIdx.x] += t;
        __syncthreads();
    }
    const int base = sp[255];
    const int i = blockIdx.x * 256 + threadIdx.x;
    if (i < N) {
        const int r = lscan[i] + base;
        rowptr[i] = r;
        cursor[i] = r;
    }
    if (i == 0) rowptr[N] = E;
}

__global__ void fill_kernel(const int* __restrict__ src, const int* __restrict__ dst,
                            int* __restrict__ cursor, int* __restrict__ eidx, int E) {
    const int e = blockIdx.x * blockDim.x + threadIdx.x;
    if (e < E) {
        const int pos = atomicAdd(&cursor[dst[e]], 1);
        eidx[pos] = src[e];
    }
}

// =============================================================================
// Gather (layer 0): agg0[n] = sum x[src], warp-per-node, C4=16
// =============================================================================
__global__ void gather0_kernel(const int* __restrict__ rowptr, const int* __restrict__ eidx,
                               const float4* __restrict__ feat, float4* __restrict__ agg,
                               int N) {
    const int g = threadIdx.x >> 5;
    const int lane = threadIdx.x & 31;
    const int node = blockIdx.x * 8 + g;
    if (node >= N) return;
    const int c  = lane & 15;
    const int eo = lane >> 4;
    const int beg = rowptr[node];
    const int end = rowptr[node + 1];
    float4 acc = make_float4(0.f, 0.f, 0.f, 0.f);
    int e = beg + eo;
    for (; e + 2 < end; e += 4) {
        const int s0 = eidx[e];
        const int s1 = eidx[e + 2];
        const float4 v0 = feat[(size_t)s0 * 16 + c];
        const float4 v1 = feat[(size_t)s1 * 16 + c];
        acc.x += v0.x + v1.x; acc.y += v0.y + v1.y;
        acc.z += v0.z + v1.z; acc.w += v0.w + v1.w;
    }
    if (e < end) {
        const int s = eidx[e];
        const float4 v = feat[(size_t)s * 16 + c];
        acc.x += v.x; acc.y += v.y; acc.z += v.z; acc.w += v.w;
    }
    acc.x += __shfl_xor_sync(0xFFFFFFFF, acc.x, 16);
    acc.y += __shfl_xor_sync(0xFFFFFFFF, acc.y, 16);
    acc.z += __shfl_xor_sync(0xFFFFFFFF, acc.z, 16);
    acc.w += __shfl_xor_sync(0xFFFFFFFF, acc.w, 16);
    if (eo == 0) agg[(size_t)node * 16 + c] = acc;
}

// =============================================================================
// Gather (layer 1) with fused bn+relu: agg1[n] = sum relu(bn(h0[src])), C4=32
// =============================================================================
__global__ void gather1_kernel(const int* __restrict__ rowptr, const int* __restrict__ eidx,
                               const float4* __restrict__ h0,
                               const float* __restrict__ stats,
                               const float* __restrict__ gamma,
                               const float* __restrict__ beta, float invN,
                               float4* __restrict__ agg, int N) {
    __shared__ float sbn[256];
    if (threadIdx.x < 128) {
        const float2 p = bn_coef(stats, gamma, beta, invN, threadIdx.x);
        sbn[threadIdx.x] = p.x;
        sbn[128 + threadIdx.x] = p.y;
    }
    __syncthreads();
    const int g = threadIdx.x >> 5;
    const int c = threadIdx.x & 31;
    const int node = blockIdx.x * 8 + g;
    if (node >= N) return;
    const float sc0 = sbn[c * 4 + 0], sh0 = sbn[128 + c * 4 + 0];
    const float sc1 = sbn[c * 4 + 1], sh1 = sbn[128 + c * 4 + 1];
    const float sc2 = sbn[c * 4 + 2], sh2 = sbn[128 + c * 4 + 2];
    const float sc3 = sbn[c * 4 + 3], sh3 = sbn[128 + c * 4 + 3];
    const int beg = rowptr[node];
    const int end = rowptr[node + 1];
    float4 acc = make_float4(0.f, 0.f, 0.f, 0.f);
    int e = beg;
    for (; e + 3 < end; e += 4) {
        const int s0 = eidx[e], s1 = eidx[e + 1], s2 = eidx[e + 2], s3 = eidx[e + 3];
        const float4 v0 = h0[(size_t)s0 * 32 + c];
        const float4 v1 = h0[(size_t)s1 * 32 + c];
        const float4 v2 = h0[(size_t)s2 * 32 + c];
        const float4 v3 = h0[(size_t)s3 * 32 + c];
        acc.x += fmaxf(fmaf(v0.x, sc0, sh0), 0.f) + fmaxf(fmaf(v1.x, sc0, sh0), 0.f)
               + fmaxf(fmaf(v2.x, sc0, sh0), 0.f) + fmaxf(fmaf(v3.x, sc0, sh0), 0.f);
        acc.y += fmaxf(fmaf(v0.y, sc1, sh1), 0.f) + fmaxf(fmaf(v1.y, sc1, sh1), 0.f)
               + fmaxf(fmaf(v2.y, sc1, sh1), 0.f) + fmaxf(fmaf(v3.y, sc1, sh1), 0.f);
        acc.z += fmaxf(fmaf(v0.z, sc2, sh2), 0.f) + fmaxf(fmaf(v1.z, sc2, sh2), 0.f)
               + fmaxf(fmaf(v2.z, sc2, sh2), 0.f) + fmaxf(fmaf(v3.z, sc2, sh2), 0.f);
        acc.w += fmaxf(fmaf(v0.w, sc3, sh3), 0.f) + fmaxf(fmaf(v1.w, sc3, sh3), 0.f)
               + fmaxf(fmaf(v2.w, sc3, sh3), 0.f) + fmaxf(fmaf(v3.w, sc3, sh3), 0.f);
    }
    for (; e < end; e++) {
        const int s = eidx[e];
        const float4 v = h0[(size_t)s * 32 + c];
        acc.x += fmaxf(fmaf(v.x, sc0, sh0), 0.f);
        acc.y += fmaxf(fmaf(v.y, sc1, sh1), 0.f);
        acc.z += fmaxf(fmaf(v.z, sc2, sh2), 0.f);
        acc.w += fmaxf(fmaf(v.w, sc3, sh3), 0.f);
    }
    agg[(size_t)node * 32 + c] = acc;
}

// =============================================================================
// FFMA GEMM (r and layer-0): C = A@W1^T (+ B@W2^T) + bias, optional stats.
// =============================================================================
__global__ __launch_bounds__(256) void gemm_kernel(
    const float* __restrict__ A, const float* __restrict__ W1,
    const float* __restrict__ B, const float* __restrict__ W2,
    const float* __restrict__ bias, float* __restrict__ C,
    float* __restrict__ stats,
    int Nn, int K) {

    __shared__ alignas(16) ull As2[2][16 * 66];
    __shared__ alignas(16) float Ws[2][16][128];
    __shared__ float sh_sum[128];
    __shared__ float sh_sq[128];

    const int tid  = threadIdx.x;
    const int row0 = blockIdx.x * 64;
    const int warp = tid >> 5;
    const int lane = tid & 31;
    const int tm   = warp * 8;
    const int tn   = lane * 4;

    if (stats && tid < 128) { sh_sum[tid] = 0.f; sh_sq[tid] = 0.f; }
    __syncthreads();

    const int ksPerMat = K >> 4;
    const int totSteps = (B != nullptr) ? 2 * ksPerMat : ksPerMat;

    const int am  = tid >> 2;
    const int akq = (tid & 3) * 4;
    const int wn  = tid >> 1;
    const int wkq = (tid & 1) * 8;

    auto LOAD = [&](int s, float4& va, float4& vw0, float4& vw1) {
        const int mt = (s >= ksPerMat) ? 1 : 0;
        const int k0 = (s - mt * ksPerMat) << 4;
        const float* Ap = mt ? B : A;
        const float* Wp = mt ? W2 : W1;
        const int rr = row0 + am;
        va = make_float4(0.f, 0.f, 0.f, 0.f);
        if (rr < Nn) va = *(const float4*)(Ap + (size_t)rr * K + k0 + akq);
        const float* wrow = Wp + (size_t)wn * K + k0 + wkq;
        vw0 = *(const float4*)(wrow);
        vw1 = *(const float4*)(wrow + 4);
    };
    auto STORE = [&](int b, const float4& va, const float4& vw0, const float4& vw1) {
        As2[b][(akq + 0) * 66 + am] = dup2(va.x);
        As2[b][(akq + 1) * 66 + am] = dup2(va.y);
        As2[b][(akq + 2) * 66 + am] = dup2(va.z);
        As2[b][(akq + 3) * 66 + am] = dup2(va.w);
        Ws[b][wkq + 0][wn] = vw0.x; Ws[b][wkq + 1][wn] = vw0.y;
        Ws[b][wkq + 2][wn] = vw0.z; Ws[b][wkq + 3][wn] = vw0.w;
        Ws[b][wkq + 4][wn] = vw1.x; Ws[b][wkq + 5][wn] = vw1.y;
        Ws[b][wkq + 6][wn] = vw1.z; Ws[b][wkq + 7][wn] = vw1.w;
    };

    ull acc2[8][2];
#pragma unroll
    for (int i = 0; i < 8; i++) { acc2[i][0] = 0ull; acc2[i][1] = 0ull; }

    {
        float4 va, vw0, vw1;
        LOAD(0, va, vw0, vw1);
        STORE(0, va, vw0, vw1);
    }
    __syncthreads();

    for (int s = 0; s < totSteps; s++) {
        const int cur = s & 1;
        float4 va, vw0, vw1;
        const bool more = (s + 1 < totSteps);
        if (more) LOAD(s + 1, va, vw0, vw1);
#pragma unroll
        for (int kk = 0; kk < 16; kk++) {
            const ulonglong2* ap = (const ulonglong2*)&As2[cur][kk * 66 + tm];
            const ulonglong2 a01 = ap[0];
            const ulonglong2 a23 = ap[1];
            const ulonglong2 a45 = ap[2];
            const ulonglong2 a67 = ap[3];
            W4 w;
            w.v = *(const float4*)&Ws[cur][kk][tn];
            FMA2(acc2[0][0], a01.x, w.u[0]); FMA2(acc2[0][1], a01.x, w.u[1]);
            FMA2(acc2[1][0], a01.y, w.u[0]); FMA2(acc2[1][1], a01.y, w.u[1]);
            FMA2(acc2[2][0], a23.x, w.u[0]); FMA2(acc2[2][1], a23.x, w.u[1]);
            FMA2(acc2[3][0], a23.y, w.u[0]); FMA2(acc2[3][1], a23.y, w.u[1]);
            FMA2(acc2[4][0], a45.x, w.u[0]); FMA2(acc2[4][1], a45.x, w.u[1]);
            FMA2(acc2[5][0], a45.y, w.u[0]); FMA2(acc2[5][1], a45.y, w.u[1]);
            FMA2(acc2[6][0], a67.x, w.u[0]); FMA2(acc2[6][1], a67.x, w.u[1]);
            FMA2(acc2[7][0], a67.y, w.u[0]); FMA2(acc2[7][1], a67.y, w.u[1]);
        }
        if (more) STORE(cur ^ 1, va, vw0, vw1);
        __syncthreads();
    }

    const float bb0 = bias ? bias[tn]     : 0.f;
    const float bb1 = bias ? bias[tn + 1] : 0.f;
    const float bb2 = bias ? bias[tn + 2] : 0.f;
    const float bb3 = bias ? bias[tn + 3] : 0.f;
    float psum[4] = {0.f, 0.f, 0.f, 0.f};
    float psq[4]  = {0.f, 0.f, 0.f, 0.f};
#pragma unroll
    for (int i = 0; i < 8; i++) {
        const int r = row0 + tm + i;
        if (r < Nn) {
            F2 p0, p1;
            p0.u = acc2[i][0];
            p1.u = acc2[i][1];
            float4 o;
            o.x = p0.f.x + bb0; o.y = p0.f.y + bb1;
            o.z = p1.f.x + bb2; o.w = p1.f.y + bb3;
            *(float4*)(C + (size_t)r * 128 + tn) = o;
            psum[0] += o.x; psum[1] += o.y; psum[2] += o.z; psum[3] += o.w;
            psq[0] += o.x * o.x; psq[1] += o.y * o.y;
            psq[2] += o.z * o.z; psq[3] += o.w * o.w;
        }
    }
    if (stats) {
#pragma unroll
        for (int j = 0; j < 4; j++) {
            atomicAdd(&sh_sum[tn + j], psum[j]);
            atomicAdd(&sh_sq[tn + j], psq[j]);
        }
        __syncthreads();
        if (tid < 128) {
            atomicAdd(&stats[tid], sh_sum[tid]);
            atomicAdd(&stats[128 + tid], sh_sq[tid]);
        }
    }
}

// =============================================================================
// HYBRID dual-pipe GEMM (K=128): C = f(A)@W^T [+C if accumC] [+bias].
// Per-CTA role = blockIdx%3: role 0 -> HMMA path (128 rows, 3-term bf16),
// roles 1,2 -> FFMA path (64 rows each). Group g = blockIdx/3 covers rows
// [g*256, g*256+256). 2 CTAs/SM forced so HMMA+FFMA CTAs co-reside and the
// tensor + fp32 pipes run in parallel. f = relu(bn(.)) if bnStats.
// =============================================================================
__global__ __launch_bounds__(256, 2) void hybrid_kernel(
    const float* __restrict__ A, const float* __restrict__ Wf,
    const __nv_bfloat16* __restrict__ Whl,
    const float* __restrict__ bias, float* __restrict__ C,
    float* __restrict__ stats, const float* __restrict__ bnStats,
    const float* __restrict__ gamma, const float* __restrict__ beta, float invN,
    int Nn, int accumC) {

    extern __shared__ char dsm[];
    __shared__ float sh_sum[128];
    __shared__ float sh_sq[128];
    __shared__ float sbn[256];

    const int tid  = threadIdx.x;
    const int grp  = blockIdx.x / 3;
    const int role = blockIdx.x % 3;

    if (stats && tid < 128) { sh_sum[tid] = 0.f; sh_sq[tid] = 0.f; }
    if (bnStats && tid < 128) {
        const float2 p = bn_coef(bnStats, gamma, beta, invN, tid);
        sbn[tid] = p.x;
        sbn[128 + tid] = p.y;
    }
    __syncthreads();

    if (role == 0) {
        // ================= HMMA path: rows [grp*256, grp*256+128) =================
        const int lane = tid & 31, wid = tid >> 5;
        const int g = lane >> 2, t = lane & 3;
        const int mrow = (wid >> 2) * 64;
        const int ncol = (wid & 3) * 32;
        const int row0 = grp * 256;

        const __nv_bfloat16* Whi = Whl;
        const __nv_bfloat16* Wlo = Whl + 128 * 128;

        float acc[4][4][4];
#pragma unroll
        for (int a = 0; a < 4; a++)
#pragma unroll
            for (int b = 0; b < 4; b++)
#pragma unroll
                for (int c = 0; c < 4; c++) acc[a][b][c] = 0.f;

        auto LDGC = [&](int kc, float4* ar, uint2* whr, uint2* wlr) {
#pragma unroll
            for (int p = 0; p < 4; p++) {
                const int idx = tid + p * 256;
                const int row = idx >> 3;
                const int kq  = (idx & 7) * 4;
                const int gr  = row0 + row;
                float4 v = make_float4(0.f, 0.f, 0.f, 0.f);
                if (gr < Nn) v = *(const float4*)(A + (size_t)gr * 128 + kc * 32 + kq);
                if (bnStats) {
                    const int cc = kc * 32 + kq;
                    v.x = fmaxf(fmaf(v.x, sbn[cc + 0], sbn[128 + cc + 0]), 0.f);
                    v.y = fmaxf(fmaf(v.y, sbn[cc + 1], sbn[128 + cc + 1]), 0.f);
                    v.z = fmaxf(fmaf(v.z, sbn[cc + 2], sbn[128 + cc + 2]), 0.f);
                    v.w = fmaxf(fmaf(v.w, sbn[cc + 3], sbn[128 + cc + 3]), 0.f);
                }
                ar[p] = v;
                const size_t wo = (size_t)row * 128 + kc * 32 + kq;
                whr[p] = *(const uint2*)(Whi + wo);
                wlr[p] = *(const uint2*)(Wlo + wo);
            }
        };
        auto STSC = [&](int b, const float4* ar, const uint2* whr, const uint2* wlr) {
            char* base = dsm + b * 40960;
            __nv_bfloat16* pAh = (__nv_bfloat16*)(base);
            __nv_bfloat16* pAl = (__nv_bfloat16*)(base + 10240);
            __nv_bfloat16* pWh = (__nv_bfloat16*)(base + 20480);
            __nv_bfloat16* pWl = (__nv_bfloat16*)(base + 30720);
#pragma unroll
            for (int p = 0; p < 4; p++) {
                const int idx = tid + p * 256;
                const int row = idx >> 3;
                const int kq  = (idx & 7) * 4;
                const int so  = row * 40 + kq;
                const float4 v = ar[p];
                const float hx = __bfloat162float(__float2bfloat16(v.x));
                const float hy = __bfloat162float(__float2bfloat16(v.y));
                const float hz = __bfloat162float(__float2bfloat16(v.z));
                const float hw = __bfloat162float(__float2bfloat16(v.w));
                *(uint2*)(pAh + so) = make_uint2(bpack(v.x, v.y), bpack(v.z, v.w));
                *(uint2*)(pAl + so) = make_uint2(bpack(v.x - hx, v.y - hy),
                                                 bpack(v.z - hz, v.w - hw));
                *(uint2*)(pWh + so) = whr[p];
                *(uint2*)(pWl + so) = wlr[p];
            }
        };
        auto COMPUTE = [&](int b) {
            char* base = dsm + b * 40960;
            const __nv_bfloat16* pAh = (const __nv_bfloat16*)(base);
            const __nv_bfloat16* pAl = (const __nv_bfloat16*)(base + 10240);
            const __nv_bfloat16* pWh = (const __nv_bfloat16*)(base + 20480);
            const __nv_bfloat16* pWl = (const __nv_bfloat16*)(base + 30720);
#pragma unroll
            for (int ks = 0; ks < 2; ks++) {
                const int k0 = ks * 16;
                u32 bh[4][2], bl[4][2];
#pragma unroll
                for (int nt = 0; nt < 4; nt++) {
                    const int nb = (ncol + nt * 8 + g) * 40 + k0 + t * 2;
                    bh[nt][0] = *(const u32*)(pWh + nb);
                    bh[nt][1] = *(const u32*)(pWh + nb + 8);
                    bl[nt][0] = *(const u32*)(pWl + nb);
                    bl[nt][1] = *(const u32*)(pWl + nb + 8);
                }
#pragma unroll
                for (int mt = 0; mt < 4; mt++) {
                    const int ab = (mrow + mt * 16 + g) * 40 + k0 + t * 2;
                    u32 ah[4], al[4];
                    ah[0] = *(const u32*)(pAh + ab);
                    ah[1] = *(const u32*)(pAh + ab + 8 * 40);
                    ah[2] = *(const u32*)(pAh + ab + 8);
                    ah[3] = *(const u32*)(pAh + ab + 8 * 40 + 8);
                    al[0] = *(const u32*)(pAl + ab);
                    al[1] = *(const u32*)(pAl + ab + 8 * 40);
                    al[2] = *(const u32*)(pAl + ab + 8);
                    al[3] = *(const u32*)(pAl + ab + 8 * 40 + 8);
#pragma unroll
                    for (int nt = 0; nt < 4; nt++) {
                        MMA_BF16(acc[mt][nt], ah, bh[nt]);
                        MMA_BF16(acc[mt][nt], ah, bl[nt]);
                        MMA_BF16(acc[mt][nt], al, bh[nt]);
                    }
                }
            }
        };

        {
            float4 ar[4]; uint2 whr[4], wlr[4];
            LDGC(0, ar, whr, wlr);
            STSC(0, ar, whr, wlr);
        }
        __syncthreads();
        for (int c = 0; c < 4; c++) {
            float4 ar[4]; uint2 whr[4], wlr[4];
            const bool more = (c < 3);
            if (more) LDGC(c + 1, ar, whr, wlr);
            COMPUTE(c & 1);
            if (more) STSC((c + 1) & 1, ar, whr, wlr);
            __syncthreads();
        }

        // epilogue
        float bcol[4][2];
#pragma unroll
        for (int nt = 0; nt < 4; nt++) {
            const int c = ncol + nt * 8 + t * 2;
            bcol[nt][0] = bias ? __ldg(bias + c)     : 0.f;
            bcol[nt][1] = bias ? __ldg(bias + c + 1) : 0.f;
        }
        float psum[4][2] = {}, psq[4][2] = {};
#pragma unroll
        for (int mt = 0; mt < 4; mt++) {
            const int r0 = row0 + mrow + mt * 16 + g;
            const int r1 = r0 + 8;
#pragma unroll
            for (int nt = 0; nt < 4; nt++) {
                const int c = ncol + nt * 8 + t * 2;
                if (r0 < Nn) {
                    float2 o;
                    o.x = acc[mt][nt][0] + bcol[nt][0];
                    o.y = acc[mt][nt][1] + bcol[nt][1];
                    if (accumC) {
                        const float2 prev = *(const float2*)(C + (size_t)r0 * 128 + c);
                        o.x += prev.x; o.y += prev.y;
                    }
                    *(float2*)(C + (size_t)r0 * 128 + c) = o;
                    psum[nt][0] += o.x; psum[nt][1] += o.y;
                    psq[nt][0] += o.x * o.x; psq[nt][1] += o.y * o.y;
                }
                if (r1 < Nn) {
                    float2 o;
                    o.x = acc[mt][nt][2] + bcol[nt][0];
                    o.y = acc[mt][nt][3] + bcol[nt][1];
                    if (accumC) {
                        const float2 prev = *(const float2*)(C + (size_t)r1 * 128 + c);
                        o.x += prev.x; o.y += prev.y;
                    }
                    *(float2*)(C + (size_t)r1 * 128 + c) = o;
                    psum[nt][0] += o.x; psum[nt][1] += o.y;
                    psq[nt][0] += o.x * o.x; psq[nt][1] += o.y * o.y;
                }
            }
        }
        if (stats) {
#pragma unroll
            for (int nt = 0; nt < 4; nt++) {
                const int c = ncol + nt * 8 + t * 2;
                atomicAdd(&sh_sum[c], psum[nt][0]);
                atomicAdd(&sh_sum[c + 1], psum[nt][1]);
                atomicAdd(&sh_sq[c], psq[nt][0]);
                atomicAdd(&sh_sq[c + 1], psq[nt][1]);
            }
            __syncthreads();
            if (tid < 128) {
                atomicAdd(&stats[tid], sh_sum[tid]);
                atomicAdd(&stats[128 + tid], sh_sq[tid]);
            }
        }
    } else {
        // ============ FFMA path: rows [grp*256+128+(role-1)*64, +64) ============
        ull* As2 = (ull*)dsm;                        // 2 x 16*66 ull = 16896 B
        float (*Ws)[16][128] = (float(*)[16][128])(dsm + 16896);  // 2 x 8192 B
        const int row0 = grp * 256 + 128 + (role - 1) * 64;
        const int warp = tid >> 5;
        const int lane = tid & 31;
        const int tm   = warp * 8;
        const int tn   = lane * 4;

        const int am  = tid >> 2;
        const int akq = (tid & 3) * 4;
        const int wn  = tid >> 1;
        const int wkq = (tid & 1) * 8;

        auto LOAD = [&](int s, float4& va, float4& vw0, float4& vw1) {
            const int k0 = s << 4;
            const int rr = row0 + am;
            va = make_float4(0.f, 0.f, 0.f, 0.f);
            if (rr < Nn) va = *(const float4*)(A + (size_t)rr * 128 + k0 + akq);
            if (bnStats) {
                const int cc = k0 + akq;
                va.x = fmaxf(fmaf(va.x, sbn[cc + 0], sbn[128 + cc + 0]), 0.f);
                va.y = fmaxf(fmaf(va.y, sbn[cc + 1], sbn[128 + cc + 1]), 0.f);
                va.z = fmaxf(fmaf(va.z, sbn[cc + 2], sbn[128 + cc + 2]), 0.f);
                va.w = fmaxf(fmaf(va.w, sbn[cc + 3], sbn[128 + cc + 3]), 0.f);
            }
            const float* wrow = Wf + (size_t)wn * 128 + k0 + wkq;
            vw0 = *(const float4*)(wrow);
            vw1 = *(const float4*)(wrow + 4);
        };
        auto STORE = [&](int b, const float4& va, const float4& vw0, const float4& vw1) {
            ull* asb = As2 + b * (16 * 66);
            asb[(akq + 0) * 66 + am] = dup2(va.x);
            asb[(akq + 1) * 66 + am] = dup2(va.y);
            asb[(akq + 2) * 66 + am] = dup2(va.z);
            asb[(akq + 3) * 66 + am] = dup2(va.w);
            Ws[b][wkq + 0][wn] = vw0.x; Ws[b][wkq + 1][wn] = vw0.y;
            Ws[b][wkq + 2][wn] = vw0.z; Ws[b][wkq + 3][wn] = vw0.w;
            Ws[b][wkq + 4][wn] = vw1.x; Ws[b][wkq + 5][wn] = vw1.y;
            Ws[b][wkq + 6][wn] = vw1.z; Ws[b][wkq + 7][wn] = vw1.w;
        };

        ull acc2[8][2];
#pragma unroll
        for (int i = 0; i < 8; i++) { acc2[i][0] = 0ull; acc2[i][1] = 0ull; }

        {
            float4 va, vw0, vw1;
            LOAD(0, va, vw0, vw1);
            STORE(0, va, vw0, vw1);
        }
        __syncthreads();

        for (int s = 0; s < 8; s++) {
            const int cur = s & 1;
            float4 va, vw0, vw1;
            const bool more = (s + 1 < 8);
            if (more) LOAD(s + 1, va, vw0, vw1);
            const ull* asb = As2 + cur * (16 * 66);
#pragma unroll
            for (int kk = 0; kk < 16; kk++) {
                const ulonglong2* ap = (const ulonglong2*)&asb[kk * 66 + tm];
                const ulonglong2 a01 = ap[0];
                const ulonglong2 a23 = ap[1];
                const ulonglong2 a45 = ap[2];
                const ulonglong2 a67 = ap[3];
                W4 w;
                w.v = *(const float4*)&Ws[cur][kk][tn];
                FMA2(acc2[0][0], a01.x, w.u[0]); FMA2(acc2[0][1], a01.x, w.u[1]);
                FMA2(acc2[1][0], a01.y, w.u[0]); FMA2(acc2[1][1], a01.y, w.u[1]);
                FMA2(acc2[2][0], a23.x, w.u[0]); FMA2(acc2[2][1], a23.x, w.u[1]);
                FMA2(acc2[3][0], a23.y, w.u[0]); FMA2(acc2[3][1], a23.y, w.u[1]);
                FMA2(acc2[4][0], a45.x, w.u[0]); FMA2(acc2[4][1], a45.x, w.u[1]);
                FMA2(acc2[5][0], a45.y, w.u[0]); FMA2(acc2[5][1], a45.y, w.u[1]);
                FMA2(acc2[6][0], a67.x, w.u[0]); FMA2(acc2[6][1], a67.x, w.u[1]);
                FMA2(acc2[7][0], a67.y, w.u[0]); FMA2(acc2[7][1], a67.y, w.u[1]);
            }
            if (more) STORE(cur ^ 1, va, vw0, vw1);
            __syncthreads();
        }

        const float bb0 = bias ? bias[tn]     : 0.f;
        const float bb1 = bias ? bias[tn + 1] : 0.f;
        const float bb2 = bias ? bias[tn + 2] : 0.f;
        const float bb3 = bias ? bias[tn + 3] : 0.f;
        float psum[4] = {0.f, 0.f, 0.f, 0.f};
        float psq[4]  = {0.f, 0.f, 0.f, 0.f};
#pragma unroll
        for (int i = 0; i < 8; i++) {
            const int r = row0 + tm + i;
            if (r < Nn) {
                F2 p0, p1;
                p0.u = acc2[i][0];
                p1.u = acc2[i][1];
                float4 o;
                o.x = p0.f.x + bb0; o.y = p0.f.y + bb1;
                o.z = p1.f.x + bb2; o.w = p1.f.y + bb3;
                if (accumC) {
                    const float4 prev = *(const float4*)(C + (size_t)r * 128 + tn);
                    o.x += prev.x; o.y += prev.y; o.z += prev.z; o.w += prev.w;
                }
                *(float4*)(C + (size_t)r * 128 + tn) = o;
                psum[0] += o.x; psum[1] += o.y; psum[2] += o.z; psum[3] += o.w;
                psq[0] += o.x * o.x; psq[1] += o.y * o.y;
                psq[2] += o.z * o.z; psq[3] += o.w * o.w;
            }
        }
        if (stats) {
#pragma unroll
            for (int j = 0; j < 4; j++) {
                atomicAdd(&sh_sum[tn + j], psum[j]);
                atomicAdd(&sh_sq[tn + j], psq[j]);
            }
            __syncthreads();
            if (tid < 128) {
                atomicAdd(&stats[tid], sh_sum[tid]);
                atomicAdd(&stats[128 + tid], sh_sq[tid]);
            }
        }
    }
}

// ---------------- out = relu(bn1(h1) + r), bn coefs computed in-block ----------------
__global__ void final_kernel(const float4* __restrict__ h1,
                             const float* __restrict__ stats,
                             const float* __restrict__ gamma,
                             const float* __restrict__ beta, float invN,
                             const float4* __restrict__ r, float4* __restrict__ out,
                             int total4) {
    __shared__ float sbn[256];
    if (threadIdx.x < 128) {
        const float2 p = bn_coef(stats, gamma, beta, invN, threadIdx.x);
        sbn[threadIdx.x] = p.x;
        sbn[128 + threadIdx.x] = p.y;
    }
    __syncthreads();
    const int i = blockIdx.x * blockDim.x + threadIdx.x;
    if (i >= total4) return;
    const int c = (i & 31) * 4;
    const float4 v = h1[i];
    const float4 rv = r[i];
    float4 o;
    o.x = fmaxf(fmaf(v.x, sbn[c + 0], sbn[128 + c + 0]) + rv.x, 0.f);
    o.y = fmaxf(fmaf(v.y, sbn[c + 1], sbn[128 + c + 1]) + rv.y, 0.f);
    o.z = fmaxf(fmaf(v.z, sbn[c + 2], sbn[128 + c + 2]) + rv.z, 0.f);
    o.w = fmaxf(fmaf(v.w, sbn[c + 3], sbn[128 + c + 3]) + rv.w, 0.f);
    out[i] = o;
}

// ---------------- launch ----------------
extern "C" void kernel_launch(void* const* d_in, const int* in_sizes, int n_in,
                              void* d_out, int out_size) {
    const float* x    = (const float*)d_in[0];
    const int*   ei   = (const int*)d_in[1];
    const float* Wr0  = (const float*)d_in[2];
    const float* Wn0  = (const float*)d_in[3];
    const float* b0   = (const float*)d_in[4];
    const float* g0   = (const float*)d_in[5];
    const float* be0  = (const float*)d_in[6];
    const float* Wr1  = (const float*)d_in[7];
    const float* Wn1  = (const float*)d_in[8];
    const float* b1   = (const float*)d_in[9];
    const float* g1   = (const float*)d_in[10];
    const float* be1  = (const float*)d_in[11];
    const float* Wlin = (const float*)d_in[12];
    const float* blin = (const float*)d_in[13];
    float* out = (float*)d_out;

    const int N = in_sizes[0] / CINn;
    const int E = in_sizes[1] / 2;
    const int* src = ei;
    const int* dst = ei + E;
    const float invN = 1.0f / (float)N;

    float *agg0, *agg1, *h0, *h1, *r, *stats;
    __nv_bfloat16* wb;
    int *deg, *lscan, *part, *rowptr, *cursor, *eidx;
    cudaGetSymbolAddress((void**)&agg0,   g_agg0);
    cudaGetSymbolAddress((void**)&agg1,   g_agg1);
    cudaGetSymbolAddress((void**)&h0,     g_h0);
    cudaGetSymbolAddress((void**)&h1,     g_h1);
    cudaGetSymbolAddress((void**)&r,      g_r);
    cudaGetSymbolAddress((void**)&stats,  g_stats);
    cudaGetSymbolAddress((void**)&wb,     g_wb);
    cudaGetSymbolAddress((void**)&deg,    g_deg);
    cudaGetSymbolAddress((void**)&lscan,  g_lscan);
    cudaGetSymbolAddress((void**)&part,   g_part);
    cudaGetSymbolAddress((void**)&rowptr, g_rowptr);
    cudaGetSymbolAddress((void**)&cursor, g_cursor);
    cudaGetSymbolAddress((void**)&eidx,   g_eidx);

    cudaFuncSetAttribute(hybrid_kernel, cudaFuncAttributeMaxDynamicSharedMemorySize, 81920);

    // side stream + fork/join events (created once)
    static cudaStream_t s2 = nullptr;
    static cudaEvent_t ev0 = nullptr, ev1 = nullptr, ev2 = nullptr, ev3 = nullptr;
    static cudaEvent_t evW = nullptr;
    if (!s2) {
        cudaStreamCreate(&s2);
        cudaEventCreateWithFlags(&ev0, cudaEventDisableTiming);
        cudaEventCreateWithFlags(&ev1, cudaEventDisableTiming);
        cudaEventCreateWithFlags(&ev2, cudaEventDisableTiming);
        cudaEventCreateWithFlags(&ev3, cudaEventDisableTiming);
        cudaEventCreateWithFlags(&evW, cudaEventDisableTiming);
    }

    cudaMemsetAsync(deg,   0, (size_t)N * sizeof(int));
    cudaMemsetAsync(stats, 0, 4 * COUTn * sizeof(float));

    const int nb = (N + SCAN_B - 1) / SCAN_B;
    const int gemmBlocks = (N + 63) / 64;
    const int ngroups = (N + 255) / 256;
    const int hybBlocks = ngroups * 3;
    const int T4 = N * 32;

    // ---- fork on s2: weight prep (bf16 hi/lo) then r = x @ Wlin^T + blin ----
    cudaEventRecord(ev0, 0);
    cudaStreamWaitEvent(s2, ev0, 0);
    wprep_kernel<<<64, 256, 0, s2>>>(Wr1, wb, 128 * 128);
    wprep_kernel<<<64, 256, 0, s2>>>(Wn1, wb + 2 * 128 * 128, 128 * 128);
    cudaEventRecord(evW, s2);
    gemm_kernel<<<gemmBlocks, 256, 0, s2>>>(x, Wlin, nullptr, nullptr, blin, r,
                                            nullptr, N, CINn);
    cudaEventRecord(ev1, s2);

    // ---- main: CSR build + layer-0 aggregation ----
    hist_kernel<<<(E + 255) / 256, 256>>>(dst, deg, E);
    scan1_kernel<<<nb, SCAN_B>>>(deg, lscan, part, N);
    scan3_kernel<<<(N + 255) / 256, 256>>>(lscan, part, rowptr, cursor, N, E, nb);
    fill_kernel<<<(E + 255) / 256, 256>>>(src, dst, cursor, eidx, E);
    gather0_kernel<<<(N + 7) / 8, 256>>>(rowptr, eidx, (const float4*)x,
                                         (float4*)agg0, N);

    // h0 = x @ Wr0^T + agg0 @ Wn0^T + b0 (+ fused BN stats -> stats[0:256])
    gemm_kernel<<<gemmBlocks, 256>>>(x, Wr0, agg0, Wn0, b0, h0, stats, N, CINn);

    // ---- fork: gather1 (needs h0, stats0) on side stream ----
    cudaEventRecord(ev2, 0);
    cudaStreamWaitEvent(s2, ev2, 0);
    gather1_kernel<<<(N + 7) / 8, 256, 0, s2>>>(rowptr, eidx, (const float4*)h0,
                                                stats, g0, be0, invN,
                                                (float4*)agg1, N);
    cudaEventRecord(ev3, s2);

    // ---- main (∥ gather1): h1 = relu(bn0(h0)) @ Wr1^T + b1 (HYBRID dual-pipe) ----
    cudaStreamWaitEvent(0, evW, 0);
    hybrid_kernel<<<hybBlocks, 256, 81920>>>(h0, Wr1, wb, b1, h1,
                                             nullptr, stats, g0, be0, invN, N, 0);

    // ---- join, then h1 += agg1 @ Wn1^T (HYBRID, + BN stats -> stats[256:512]) ----
    cudaStreamWaitEvent(0, ev3, 0);
    hybrid_kernel<<<hybBlocks, 256, 81920>>>(agg1, Wn1, wb + 2 * 128 * 128, nullptr, h1,
                                             stats + 2 * COUTn, nullptr, nullptr, nullptr,
                                             0.f, N, 1);

    // ---- join r, then out = relu(bn1(h1) + r) ----
    cudaStreamWaitEvent(0, ev1, 0);
    final_kernel<<<(T4 + 255) / 256, 256>>>((const float4*)h1,
                                            stats + 2 * COUTn, g1, be1, invN,
                                            (const float4*)r, (float4*)out, T4);
}